// round 1
// baseline (speedup 1.0000x reference)
#include <cuda_runtime.h>
#include <math.h>

// Problem constants
#define D_MODEL 2048
#define QHEADS  32
#define KVHEADS 8
#define HD      64
#define BATCH   2
#define SEQ     2048
#define NROWS   (BATCH * SEQ)      // 4096
#define KVD     (KVHEADS * HD)     // 512

// ---------------------------------------------------------------------------
// Scratch (static device globals; no runtime allocation allowed)
// ---------------------------------------------------------------------------
__device__ float g_Q[(size_t)NROWS * D_MODEL];   // projected+roped Q  [b,s,h*64+d]
__device__ float g_K[(size_t)NROWS * KVD];       // projected+roped K  [b,s,kvh*64+d]
__device__ float g_V[(size_t)NROWS * KVD];       // projected V
__device__ float g_AO[(size_t)NROWS * D_MODEL];  // attention output   [b,s,h*64+d]

// ---------------------------------------------------------------------------
// SGEMM: C[M,N] = A[M,K] @ B[K,N] (+ bias), row-major, all dims multiples of tile
// 128x128 block tile, 8x8 per thread, BK=8, 256 threads
// ---------------------------------------------------------------------------
#define BM 128
#define BN 128
#define BK 8
#define TM 8
#define TN 8

__global__ void __launch_bounds__(256) sgemm_kernel(
    const float* __restrict__ A, const float* __restrict__ B,
    const float* __restrict__ bias, float* __restrict__ C,
    int M, int N, int K)
{
    __shared__ float As[BK][BM];
    __shared__ float Bs[BK][BN];

    const int tid = threadIdx.x;
    const int tx = tid % 16;           // 0..15  (cols)
    const int ty = tid / 16;           // 0..15  (rows)
    const int rowBase = blockIdx.y * BM;
    const int colBase = blockIdx.x * BN;

    // load mapping: A tile is BM x BK (1024 floats), B tile is BK x BN (1024 floats)
    const int aRow = tid >> 1;         // 0..127
    const int aCol = (tid & 1) * 4;    // 0 or 4
    const int bRow = tid >> 5;         // 0..7
    const int bCol = (tid & 31) * 4;   // 0..124

    const float* Ag = A + (size_t)(rowBase + aRow) * K + aCol;
    const float* Bg = B + (size_t)bRow * N + colBase + bCol;

    float acc[TM][TN];
#pragma unroll
    for (int i = 0; i < TM; i++)
#pragma unroll
        for (int j = 0; j < TN; j++) acc[i][j] = 0.0f;

    for (int k0 = 0; k0 < K; k0 += BK) {
        float4 a4 = *(const float4*)(Ag + k0);
        As[aCol + 0][aRow] = a4.x;
        As[aCol + 1][aRow] = a4.y;
        As[aCol + 2][aRow] = a4.z;
        As[aCol + 3][aRow] = a4.w;
        float4 b4 = *(const float4*)(Bg + (size_t)k0 * N);
        *(float4*)&Bs[bRow][bCol] = b4;
        __syncthreads();

#pragma unroll
        for (int kk = 0; kk < BK; kk++) {
            float ar[TM], br[TN];
            *(float4*)&ar[0] = *(const float4*)&As[kk][ty * TM];
            *(float4*)&ar[4] = *(const float4*)&As[kk][ty * TM + 4];
            *(float4*)&br[0] = *(const float4*)&Bs[kk][tx * TN];
            *(float4*)&br[4] = *(const float4*)&Bs[kk][tx * TN + 4];
#pragma unroll
            for (int i = 0; i < TM; i++)
#pragma unroll
                for (int j = 0; j < TN; j++)
                    acc[i][j] += ar[i] * br[j];
        }
        __syncthreads();
    }

#pragma unroll
    for (int i = 0; i < TM; i++) {
        const int r = rowBase + ty * TM + i;
        float* Crow = C + (size_t)r * N + colBase + tx * TN;
        if (bias) {
            const float* brow = bias + colBase + tx * TN;
#pragma unroll
            for (int j = 0; j < TN; j++) Crow[j] = acc[i][j] + brow[j];
        } else {
#pragma unroll
            for (int j = 0; j < TN; j++) Crow[j] = acc[i][j];
        }
    }
}

// ---------------------------------------------------------------------------
// RoPE (in place). X: [NROWS, nheads*64]. Each thread handles one (row, head,
// half-index) pair: out[j] = x[j]*cos - x[j+32]*sin ; out[j+32] = x[j+32]*cos + x[j]*sin
// freq computed in double for stability (matches f32 reference to ~1e-7 phase rel).
// ---------------------------------------------------------------------------
__global__ void rope_kernel(float* __restrict__ X, int nheads, int total)
{
    int idx = blockIdx.x * blockDim.x + threadIdx.x;
    if (idx >= total) return;
    const int half = idx & 31;          // 0..31
    const int t = idx >> 5;
    const int head = t % nheads;
    const int row = t / nheads;         // b*SEQ + s
    const int pos = row & (SEQ - 1);

    double inv_freq = pow(1000000.0, -(double)half / 32.0);
    double freq = (double)pos * inv_freq;
    float c = (float)cos(freq);
    float s = (float)sin(freq);

    float* base = X + (size_t)row * nheads * HD + head * HD;
    float x1 = base[half];
    float x2 = base[half + 32];
    base[half]      = x1 * c - x2 * s;
    base[half + 32] = x2 * c + x1 * s;
}

// ---------------------------------------------------------------------------
// Attention: non-causal, GQA (head h uses kv head h % KVHEADS), online softmax.
// Block = 128 threads = 128 query rows; each thread keeps q[64], o[64] in regs.
// Key/Value streamed through smem in 64-key tiles (broadcast reads, no conflicts).
// ---------------------------------------------------------------------------
#define KTILE 64

__global__ void __launch_bounds__(128) attn_kernel(
    const float* __restrict__ Q, const float* __restrict__ K,
    const float* __restrict__ V, float* __restrict__ O)
{
    __shared__ float Ks[KTILE][HD];
    __shared__ float Vs[KTILE][HD];

    const int tid = threadIdx.x;
    const int qt  = blockIdx.x;            // query tile (SEQ/128)
    const int h   = blockIdx.y;            // 0..31
    const int b   = blockIdx.z;            // 0..1
    const int kvh = h & (KVHEADS - 1);     // jnp.tile -> h % KVH
    const int srow = qt * 128 + tid;

    const float scale = 0.125f;            // 1/sqrt(64), folded into q

    float q[HD];
    {
        const float* qp = Q + ((size_t)(b * SEQ + srow)) * D_MODEL + h * HD;
#pragma unroll
        for (int d4 = 0; d4 < 16; d4++) {
            float4 v = *(const float4*)(qp + d4 * 4);
            q[d4 * 4 + 0] = v.x * scale;
            q[d4 * 4 + 1] = v.y * scale;
            q[d4 * 4 + 2] = v.z * scale;
            q[d4 * 4 + 3] = v.w * scale;
        }
    }

    float o[HD];
#pragma unroll
    for (int d = 0; d < HD; d++) o[d] = 0.0f;
    float m = -1e30f, l = 0.0f;

    const float* Kbase = K + ((size_t)b * SEQ) * KVD + kvh * HD;
    const float* Vbase = V + ((size_t)b * SEQ) * KVD + kvh * HD;

    for (int kt = 0; kt < SEQ; kt += KTILE) {
        __syncthreads();
        // 64 rows x 16 float4 = 1024 float4; 128 threads x 8 each
#pragma unroll
        for (int i = 0; i < 8; i++) {
            int e  = tid + i * 128;
            int r  = e >> 4;
            int c4 = e & 15;
            *(float4*)&Ks[r][c4 * 4] = *(const float4*)(Kbase + (size_t)(kt + r) * KVD + c4 * 4);
            *(float4*)&Vs[r][c4 * 4] = *(const float4*)(Vbase + (size_t)(kt + r) * KVD + c4 * 4);
        }
        __syncthreads();

        for (int kk = 0; kk < KTILE; kk++) {
            // 4-way split dot for ILP (break the 4-cycle FFMA dependency chain)
            float s0 = 0.f, s1 = 0.f, s2 = 0.f, s3 = 0.f;
#pragma unroll
            for (int d4 = 0; d4 < 16; d4++) {
                float4 kv = *(const float4*)&Ks[kk][d4 * 4];
                s0 += q[d4 * 4 + 0] * kv.x;
                s1 += q[d4 * 4 + 1] * kv.y;
                s2 += q[d4 * 4 + 2] * kv.z;
                s3 += q[d4 * 4 + 3] * kv.w;
            }
            float s = (s0 + s1) + (s2 + s3);

            if (s > m) {                   // rare after warmup (~ln(S) times/row)
                float corr = __expf(m - s);
                m = s;
                l *= corr;
#pragma unroll
                for (int d = 0; d < HD; d++) o[d] *= corr;
            }
            float p = __expf(s - m);
            l += p;
#pragma unroll
            for (int d4 = 0; d4 < 16; d4++) {
                float4 vv = *(const float4*)&Vs[kk][d4 * 4];
                o[d4 * 4 + 0] += p * vv.x;
                o[d4 * 4 + 1] += p * vv.y;
                o[d4 * 4 + 2] += p * vv.z;
                o[d4 * 4 + 3] += p * vv.w;
            }
        }
    }

    const float inv_l = 1.0f / l;
    float* op = O + ((size_t)(b * SEQ + srow)) * D_MODEL + h * HD;
#pragma unroll
    for (int d4 = 0; d4 < 16; d4++) {
        float4 v;
        v.x = o[d4 * 4 + 0] * inv_l;
        v.y = o[d4 * 4 + 1] * inv_l;
        v.z = o[d4 * 4 + 2] * inv_l;
        v.w = o[d4 * 4 + 3] * inv_l;
        *(float4*)(op + d4 * 4) = v;
    }
}

// ---------------------------------------------------------------------------
// kernel_launch
// Inputs: [0]=q [1]=k [2]=v [3]=attn_mask(unused by reference math) [4]=Wq
//         [5]=Wk [6]=Wv [7]=Wo [8]=bo   (all float32)
// ---------------------------------------------------------------------------
extern "C" void kernel_launch(void* const* d_in, const int* in_sizes, int n_in,
                              void* d_out, int out_size)
{
    const float* q  = (const float*)d_in[0];
    const float* k  = (const float*)d_in[1];
    const float* v  = (const float*)d_in[2];
    const float* Wq = (const float*)d_in[4];
    const float* Wk = (const float*)d_in[5];
    const float* Wv = (const float*)d_in[6];
    const float* Wo = (const float*)d_in[7];
    const float* bo = (const float*)d_in[8];
    float* out = (float*)d_out;

    float *gQ, *gK, *gV, *gAO;
    cudaGetSymbolAddress((void**)&gQ,  g_Q);
    cudaGetSymbolAddress((void**)&gK,  g_K);
    cudaGetSymbolAddress((void**)&gV,  g_V);
    cudaGetSymbolAddress((void**)&gAO, g_AO);

    // Projections
    sgemm_kernel<<<dim3(D_MODEL / BN, NROWS / BM), 256>>>(q, Wq, nullptr, gQ, NROWS, D_MODEL, D_MODEL);
    sgemm_kernel<<<dim3(KVD / BN,     NROWS / BM), 256>>>(k, Wk, nullptr, gK, NROWS, KVD, D_MODEL);
    sgemm_kernel<<<dim3(KVD / BN,     NROWS / BM), 256>>>(v, Wv, nullptr, gV, NROWS, KVD, D_MODEL);

    // RoPE on Q and K (in place)
    {
        int totQ = NROWS * QHEADS * 32;
        rope_kernel<<<(totQ + 255) / 256, 256>>>(gQ, QHEADS, totQ);
        int totK = NROWS * KVHEADS * 32;
        rope_kernel<<<(totK + 255) / 256, 256>>>(gK, KVHEADS, totK);
    }

    // Attention
    attn_kernel<<<dim3(SEQ / 128, QHEADS, BATCH), 128>>>(gQ, gK, gV, gAO);

    // Output projection + bias
    sgemm_kernel<<<dim3(D_MODEL / BN, NROWS / BM), 256>>>(gAO, Wo, bo, out, NROWS, D_MODEL, D_MODEL);
}

// round 3
// speedup vs baseline: 1.2312x; 1.2312x over previous
#include <cuda_runtime.h>
#include <cuda_bf16.h>
#include <math.h>
#include <stdint.h>

// Problem constants
#define D_MODEL 2048
#define QHEADS  32
#define KVHEADS 8
#define HD      64
#define BATCH   2
#define SEQ     2048
#define NROWS   (BATCH * SEQ)      // 4096
#define KVD     (KVHEADS * HD)     // 512

// ---------------------------------------------------------------------------
// Scratch (static device globals; no runtime allocation allowed)
// ---------------------------------------------------------------------------
__device__ float g_Q[(size_t)NROWS * D_MODEL];
__device__ float g_K[(size_t)NROWS * KVD];
__device__ float g_V[(size_t)NROWS * KVD];
__device__ float g_AO[(size_t)NROWS * D_MODEL];

// ---------------------------------------------------------------------------
// mma.sync m16n8k16 bf16 (baseline PTX, works at compute_100)
// ---------------------------------------------------------------------------
__device__ __forceinline__ void mma16816(float* c, const uint32_t* a, uint32_t b0, uint32_t b1) {
    asm volatile(
        "mma.sync.aligned.m16n8k16.row.col.f32.bf16.bf16.f32 "
        "{%0,%1,%2,%3}, {%4,%5,%6,%7}, {%8,%9}, {%0,%1,%2,%3};"
        : "+f"(c[0]), "+f"(c[1]), "+f"(c[2]), "+f"(c[3])
        : "r"(a[0]), "r"(a[1]), "r"(a[2]), "r"(a[3]), "r"(b0), "r"(b1));
}

// ---------------------------------------------------------------------------
// Split-bf16 tensor-core GEMM: C[M,N] = A[M,K] @ B[K,N] (+bias)
// Block tile 128x128, BK=32, 8 warps (4m x 2n), warp tile 32x64.
// A = A_hi + A_lo, B = B_hi + B_lo (bf16); D += AhBh + AhBl + AlBh (fp32 acc).
// ---------------------------------------------------------------------------
#define AS_STRIDE 36   // bf16 elements per smem row (pad vs 32 to spread banks)

__global__ void __launch_bounds__(256) mma_gemm_kernel(
    const float* __restrict__ A, const float* __restrict__ B,
    const float* __restrict__ bias, float* __restrict__ C,
    int M, int N, int K)
{
    __shared__ uint16_t As_hi[128][AS_STRIDE];
    __shared__ uint16_t As_lo[128][AS_STRIDE];
    __shared__ uint16_t Bs_hi[128][AS_STRIDE];   // n-major (transposed)
    __shared__ uint16_t Bs_lo[128][AS_STRIDE];

    const int tid  = threadIdx.x;
    const int lane = tid & 31;
    const int w    = tid >> 5;
    const int mw   = w >> 1;           // 0..3
    const int nw   = w & 1;            // 0..1
    const int rowBase = blockIdx.y * 128;
    const int colBase = blockIdx.x * 128;

    const int g   = lane >> 2;         // 0..7 (fragment row group)
    const int tg2 = (lane & 3) * 2;    // 0,2,4,6 (fragment k/col pair)

    float acc[2][8][4];
#pragma unroll
    for (int mt = 0; mt < 2; mt++)
#pragma unroll
        for (int nt = 0; nt < 8; nt++)
#pragma unroll
            for (int j = 0; j < 4; j++) acc[mt][nt][j] = 0.0f;

    const int nChunks = K >> 5;        // K / 32

    for (int ch = 0; ch < nChunks; ch++) {
        if (ch) __syncthreads();       // previous compute done before overwrite
        const int k0 = ch << 5;

        // ---- stage A: 128 rows x 32 cols fp32 -> hi/lo bf16 (K-major)
        {
            const float* Ag = A + (size_t)rowBase * K + k0;
#pragma unroll
            for (int i = 0; i < 8; i++) {
                const int e  = tid + i * 256;
                const int r  = e >> 4;
                const int c2 = (e & 15) * 2;
                float2 a = *(const float2*)(Ag + (size_t)r * K + c2);
                uint32_t hi2, lo2;
                asm("cvt.rn.bf16x2.f32 %0, %1, %2;" : "=r"(hi2) : "f"(a.y), "f"(a.x));
                float hx = __uint_as_float(hi2 << 16);
                float hy = __uint_as_float(hi2 & 0xFFFF0000u);
                asm("cvt.rn.bf16x2.f32 %0, %1, %2;" : "=r"(lo2) : "f"(a.y - hy), "f"(a.x - hx));
                *(uint32_t*)&As_hi[r][c2] = hi2;
                *(uint32_t*)&As_lo[r][c2] = lo2;
            }
        }
        // ---- stage B: 32 k-rows x 128 cols fp32 -> hi/lo bf16, TRANSPOSED (n-major)
        {
            const float* Bg = B + (size_t)k0 * N + colBase;
#pragma unroll
            for (int i = 0; i < 8; i++) {
                const int e  = tid + i * 256;
                const int k  = e >> 6;
                const int n0 = (e & 63) * 2;
                float2 b = *(const float2*)(Bg + (size_t)k * N + n0);
                uint32_t hi2, lo2;
                asm("cvt.rn.bf16x2.f32 %0, %1, %2;" : "=r"(hi2) : "f"(b.y), "f"(b.x));
                float hx = __uint_as_float(hi2 << 16);
                float hy = __uint_as_float(hi2 & 0xFFFF0000u);
                asm("cvt.rn.bf16x2.f32 %0, %1, %2;" : "=r"(lo2) : "f"(b.y - hy), "f"(b.x - hx));
                Bs_hi[n0][k]     = (uint16_t)(hi2 & 0xFFFF);
                Bs_hi[n0 + 1][k] = (uint16_t)(hi2 >> 16);
                Bs_lo[n0][k]     = (uint16_t)(lo2 & 0xFFFF);
                Bs_lo[n0 + 1][k] = (uint16_t)(lo2 >> 16);
            }
        }
        __syncthreads();

        // ---- compute: 2 k-steps of 16
#pragma unroll
        for (int ks = 0; ks < 2; ks++) {
            const int kk = ks * 16;
            uint32_t ahi[2][4], alo[2][4];
#pragma unroll
            for (int mt = 0; mt < 2; mt++) {
                const int r0 = mw * 32 + mt * 16 + g;
                const int c0 = kk + tg2;
                ahi[mt][0] = *(const uint32_t*)&As_hi[r0][c0];
                ahi[mt][1] = *(const uint32_t*)&As_hi[r0 + 8][c0];
                ahi[mt][2] = *(const uint32_t*)&As_hi[r0][c0 + 8];
                ahi[mt][3] = *(const uint32_t*)&As_hi[r0 + 8][c0 + 8];
                alo[mt][0] = *(const uint32_t*)&As_lo[r0][c0];
                alo[mt][1] = *(const uint32_t*)&As_lo[r0 + 8][c0];
                alo[mt][2] = *(const uint32_t*)&As_lo[r0][c0 + 8];
                alo[mt][3] = *(const uint32_t*)&As_lo[r0 + 8][c0 + 8];
            }
#pragma unroll
            for (int nt = 0; nt < 8; nt++) {
                const int col = nw * 64 + nt * 8 + g;
                const int c0  = kk + tg2;
                uint32_t bh0 = *(const uint32_t*)&Bs_hi[col][c0];
                uint32_t bh1 = *(const uint32_t*)&Bs_hi[col][c0 + 8];
                uint32_t bl0 = *(const uint32_t*)&Bs_lo[col][c0];
                uint32_t bl1 = *(const uint32_t*)&Bs_lo[col][c0 + 8];
#pragma unroll
                for (int mt = 0; mt < 2; mt++) {
                    mma16816(acc[mt][nt], ahi[mt], bh0, bh1);
                    mma16816(acc[mt][nt], ahi[mt], bl0, bl1);
                    mma16816(acc[mt][nt], alo[mt], bh0, bh1);
                }
            }
        }
    }

    // ---- epilogue: fragment (g, tg2) mapping; write float2 pairs
#pragma unroll
    for (int mt = 0; mt < 2; mt++) {
        const int r = rowBase + mw * 32 + mt * 16 + g;
#pragma unroll
        for (int nt = 0; nt < 8; nt++) {
            const int c = colBase + nw * 64 + nt * 8 + tg2;
            float bx = 0.f, by = 0.f;
            if (bias) { bx = bias[c]; by = bias[c + 1]; }
            float2 v0 = make_float2(acc[mt][nt][0] + bx, acc[mt][nt][1] + by);
            float2 v1 = make_float2(acc[mt][nt][2] + bx, acc[mt][nt][3] + by);
            *(float2*)(C + (size_t)r * N + c)       = v0;
            *(float2*)(C + (size_t)(r + 8) * N + c) = v1;
        }
    }
}

// ---------------------------------------------------------------------------
// RoPE (in place), unchanged
// ---------------------------------------------------------------------------
__global__ void rope_kernel(float* __restrict__ X, int nheads, int total)
{
    int idx = blockIdx.x * blockDim.x + threadIdx.x;
    if (idx >= total) return;
    const int half = idx & 31;
    const int t = idx >> 5;
    const int head = t % nheads;
    const int row = t / nheads;
    const int pos = row & (SEQ - 1);

    double inv_freq = pow(1000000.0, -(double)half / 32.0);
    double freq = (double)pos * inv_freq;
    float c = (float)cos(freq);
    float s = (float)sin(freq);

    float* base = X + (size_t)row * nheads * HD + head * HD;
    float x1 = base[half];
    float x2 = base[half + 32];
    base[half]      = x1 * c - x2 * s;
    base[half + 32] = x2 * c + x1 * s;
}

// ---------------------------------------------------------------------------
// Attention (fp32 streaming flash, unchanged this round)
// ---------------------------------------------------------------------------
#define KTILE 64

__global__ void __launch_bounds__(128) attn_kernel(
    const float* __restrict__ Q, const float* __restrict__ K,
    const float* __restrict__ V, float* __restrict__ O)
{
    __shared__ float Ks[KTILE][HD];
    __shared__ float Vs[KTILE][HD];

    const int tid = threadIdx.x;
    const int qt  = blockIdx.x;
    const int h   = blockIdx.y;
    const int b   = blockIdx.z;
    const int kvh = h & (KVHEADS - 1);
    const int srow = qt * 128 + tid;

    const float scale = 0.125f;

    float q[HD];
    {
        const float* qp = Q + ((size_t)(b * SEQ + srow)) * D_MODEL + h * HD;
#pragma unroll
        for (int d4 = 0; d4 < 16; d4++) {
            float4 v = *(const float4*)(qp + d4 * 4);
            q[d4 * 4 + 0] = v.x * scale;
            q[d4 * 4 + 1] = v.y * scale;
            q[d4 * 4 + 2] = v.z * scale;
            q[d4 * 4 + 3] = v.w * scale;
        }
    }

    float o[HD];
#pragma unroll
    for (int d = 0; d < HD; d++) o[d] = 0.0f;
    float m = -1e30f, l = 0.0f;

    const float* Kbase = K + ((size_t)b * SEQ) * KVD + kvh * HD;
    const float* Vbase = V + ((size_t)b * SEQ) * KVD + kvh * HD;

    for (int kt = 0; kt < SEQ; kt += KTILE) {
        __syncthreads();
#pragma unroll
        for (int i = 0; i < 8; i++) {
            int e  = tid + i * 128;
            int r  = e >> 4;
            int c4 = e & 15;
            *(float4*)&Ks[r][c4 * 4] = *(const float4*)(Kbase + (size_t)(kt + r) * KVD + c4 * 4);
            *(float4*)&Vs[r][c4 * 4] = *(const float4*)(Vbase + (size_t)(kt + r) * KVD + c4 * 4);
        }
        __syncthreads();

        for (int kk = 0; kk < KTILE; kk++) {
            float s0 = 0.f, s1 = 0.f, s2 = 0.f, s3 = 0.f;
#pragma unroll
            for (int d4 = 0; d4 < 16; d4++) {
                float4 kv = *(const float4*)&Ks[kk][d4 * 4];
                s0 += q[d4 * 4 + 0] * kv.x;
                s1 += q[d4 * 4 + 1] * kv.y;
                s2 += q[d4 * 4 + 2] * kv.z;
                s3 += q[d4 * 4 + 3] * kv.w;
            }
            float s = (s0 + s1) + (s2 + s3);

            if (s > m) {
                float corr = __expf(m - s);
                m = s;
                l *= corr;
#pragma unroll
                for (int d = 0; d < HD; d++) o[d] *= corr;
            }
            float p = __expf(s - m);
            l += p;
#pragma unroll
            for (int d4 = 0; d4 < 16; d4++) {
                float4 vv = *(const float4*)&Vs[kk][d4 * 4];
                o[d4 * 4 + 0] += p * vv.x;
                o[d4 * 4 + 1] += p * vv.y;
                o[d4 * 4 + 2] += p * vv.z;
                o[d4 * 4 + 3] += p * vv.w;
            }
        }
    }

    const float inv_l = 1.0f / l;
    float* op = O + ((size_t)(b * SEQ + srow)) * D_MODEL + h * HD;
#pragma unroll
    for (int d4 = 0; d4 < 16; d4++) {
        float4 v;
        v.x = o[d4 * 4 + 0] * inv_l;
        v.y = o[d4 * 4 + 1] * inv_l;
        v.z = o[d4 * 4 + 2] * inv_l;
        v.w = o[d4 * 4 + 3] * inv_l;
        *(float4*)(op + d4 * 4) = v;
    }
}

// ---------------------------------------------------------------------------
// kernel_launch
// ---------------------------------------------------------------------------
extern "C" void kernel_launch(void* const* d_in, const int* in_sizes, int n_in,
                              void* d_out, int out_size)
{
    const float* q  = (const float*)d_in[0];
    const float* k  = (const float*)d_in[1];
    const float* v  = (const float*)d_in[2];
    const float* Wq = (const float*)d_in[4];
    const float* Wk = (const float*)d_in[5];
    const float* Wv = (const float*)d_in[6];
    const float* Wo = (const float*)d_in[7];
    const float* bo = (const float*)d_in[8];
    float* out = (float*)d_out;

    float *gQ, *gK, *gV, *gAO;
    cudaGetSymbolAddress((void**)&gQ,  g_Q);
    cudaGetSymbolAddress((void**)&gK,  g_K);
    cudaGetSymbolAddress((void**)&gV,  g_V);
    cudaGetSymbolAddress((void**)&gAO, g_AO);

    // Projections (tensor-core split-bf16)
    mma_gemm_kernel<<<dim3(D_MODEL / 128, NROWS / 128), 256>>>(q, Wq, nullptr, gQ, NROWS, D_MODEL, D_MODEL);
    mma_gemm_kernel<<<dim3(KVD / 128,     NROWS / 128), 256>>>(k, Wk, nullptr, gK, NROWS, KVD, D_MODEL);
    mma_gemm_kernel<<<dim3(KVD / 128,     NROWS / 128), 256>>>(v, Wv, nullptr, gV, NROWS, KVD, D_MODEL);

    // RoPE on Q and K (in place)
    {
        int totQ = NROWS * QHEADS * 32;
        rope_kernel<<<(totQ + 255) / 256, 256>>>(gQ, QHEADS, totQ);
        int totK = NROWS * KVHEADS * 32;
        rope_kernel<<<(totK + 255) / 256, 256>>>(gK, KVHEADS, totK);
    }

    // Attention
    attn_kernel<<<dim3(SEQ / 128, QHEADS, BATCH), 128>>>(gQ, gK, gV, gAO);

    // Output projection + bias (tensor-core split-bf16)
    mma_gemm_kernel<<<dim3(D_MODEL / 128, NROWS / 128), 256>>>(gAO, Wo, bo, out, NROWS, D_MODEL, D_MODEL);
}

// round 4
// speedup vs baseline: 2.1232x; 1.7245x over previous
#include <cuda_runtime.h>
#include <cuda_bf16.h>
#include <math.h>
#include <stdint.h>

// Problem constants
#define D_MODEL 2048
#define QHEADS  32
#define KVHEADS 8
#define HD      64
#define BATCH   2
#define SEQ     2048
#define NROWS   (BATCH * SEQ)      // 4096
#define KVD     (KVHEADS * HD)     // 512

// ---------------------------------------------------------------------------
// Scratch
// ---------------------------------------------------------------------------
__device__ float g_Q[(size_t)NROWS * D_MODEL];
__device__ float g_K[(size_t)NROWS * KVD];
__device__ float g_V[(size_t)NROWS * KVD];
__device__ float g_AO[(size_t)NROWS * D_MODEL];

// ---------------------------------------------------------------------------
// mma.sync m16n8k16 bf16 (baseline PTX, compiles at compute_100)
// ---------------------------------------------------------------------------
__device__ __forceinline__ void mma16816(float* c, const uint32_t* a, uint32_t b0, uint32_t b1) {
    asm volatile(
        "mma.sync.aligned.m16n8k16.row.col.f32.bf16.bf16.f32 "
        "{%0,%1,%2,%3}, {%4,%5,%6,%7}, {%8,%9}, {%0,%1,%2,%3};"
        : "+f"(c[0]), "+f"(c[1]), "+f"(c[2]), "+f"(c[3])
        : "r"(a[0]), "r"(a[1]), "r"(a[2]), "r"(a[3]), "r"(b0), "r"(b1));
}

// pack (x -> lo half, y -> hi half) with hi/lo fp32 split
__device__ __forceinline__ void split2(float x, float y, uint32_t& hi, uint32_t& lo) {
    asm("cvt.rn.bf16x2.f32 %0, %1, %2;" : "=r"(hi) : "f"(y), "f"(x));
    float hx = __uint_as_float(hi << 16);
    float hy = __uint_as_float(hi & 0xFFFF0000u);
    asm("cvt.rn.bf16x2.f32 %0, %1, %2;" : "=r"(lo) : "f"(y - hy), "f"(x - hx));
}

// ---------------------------------------------------------------------------
// Split-bf16 tensor-core GEMM (unchanged from R3)
// ---------------------------------------------------------------------------
#define AS_STRIDE 36

__global__ void __launch_bounds__(256) mma_gemm_kernel(
    const float* __restrict__ A, const float* __restrict__ B,
    const float* __restrict__ bias, float* __restrict__ C,
    int M, int N, int K)
{
    __shared__ uint16_t As_hi[128][AS_STRIDE];
    __shared__ uint16_t As_lo[128][AS_STRIDE];
    __shared__ uint16_t Bs_hi[128][AS_STRIDE];
    __shared__ uint16_t Bs_lo[128][AS_STRIDE];

    const int tid  = threadIdx.x;
    const int lane = tid & 31;
    const int w    = tid >> 5;
    const int mw   = w >> 1;
    const int nw   = w & 1;
    const int rowBase = blockIdx.y * 128;
    const int colBase = blockIdx.x * 128;

    const int g   = lane >> 2;
    const int tg2 = (lane & 3) * 2;

    float acc[2][8][4];
#pragma unroll
    for (int mt = 0; mt < 2; mt++)
#pragma unroll
        for (int nt = 0; nt < 8; nt++)
#pragma unroll
            for (int j = 0; j < 4; j++) acc[mt][nt][j] = 0.0f;

    const int nChunks = K >> 5;

    for (int ch = 0; ch < nChunks; ch++) {
        if (ch) __syncthreads();
        const int k0 = ch << 5;

        {
            const float* Ag = A + (size_t)rowBase * K + k0;
#pragma unroll
            for (int i = 0; i < 8; i++) {
                const int e  = tid + i * 256;
                const int r  = e >> 4;
                const int c2 = (e & 15) * 2;
                float2 a = *(const float2*)(Ag + (size_t)r * K + c2);
                uint32_t hi2, lo2;
                split2(a.x, a.y, hi2, lo2);
                *(uint32_t*)&As_hi[r][c2] = hi2;
                *(uint32_t*)&As_lo[r][c2] = lo2;
            }
        }
        {
            const float* Bg = B + (size_t)k0 * N + colBase;
#pragma unroll
            for (int i = 0; i < 8; i++) {
                const int e  = tid + i * 256;
                const int k  = e >> 6;
                const int n0 = (e & 63) * 2;
                float2 b = *(const float2*)(Bg + (size_t)k * N + n0);
                uint32_t hi2, lo2;
                split2(b.x, b.y, hi2, lo2);
                Bs_hi[n0][k]     = (uint16_t)(hi2 & 0xFFFF);
                Bs_hi[n0 + 1][k] = (uint16_t)(hi2 >> 16);
                Bs_lo[n0][k]     = (uint16_t)(lo2 & 0xFFFF);
                Bs_lo[n0 + 1][k] = (uint16_t)(lo2 >> 16);
            }
        }
        __syncthreads();

#pragma unroll
        for (int ks = 0; ks < 2; ks++) {
            const int kk = ks * 16;
            uint32_t ahi[2][4], alo[2][4];
#pragma unroll
            for (int mt = 0; mt < 2; mt++) {
                const int r0 = mw * 32 + mt * 16 + g;
                const int c0 = kk + tg2;
                ahi[mt][0] = *(const uint32_t*)&As_hi[r0][c0];
                ahi[mt][1] = *(const uint32_t*)&As_hi[r0 + 8][c0];
                ahi[mt][2] = *(const uint32_t*)&As_hi[r0][c0 + 8];
                ahi[mt][3] = *(const uint32_t*)&As_hi[r0 + 8][c0 + 8];
                alo[mt][0] = *(const uint32_t*)&As_lo[r0][c0];
                alo[mt][1] = *(const uint32_t*)&As_lo[r0 + 8][c0];
                alo[mt][2] = *(const uint32_t*)&As_lo[r0][c0 + 8];
                alo[mt][3] = *(const uint32_t*)&As_lo[r0 + 8][c0 + 8];
            }
#pragma unroll
            for (int nt = 0; nt < 8; nt++) {
                const int col = nw * 64 + nt * 8 + g;
                const int c0  = kk + tg2;
                uint32_t bh0 = *(const uint32_t*)&Bs_hi[col][c0];
                uint32_t bh1 = *(const uint32_t*)&Bs_hi[col][c0 + 8];
                uint32_t bl0 = *(const uint32_t*)&Bs_lo[col][c0];
                uint32_t bl1 = *(const uint32_t*)&Bs_lo[col][c0 + 8];
#pragma unroll
                for (int mt = 0; mt < 2; mt++) {
                    mma16816(acc[mt][nt], ahi[mt], bh0, bh1);
                    mma16816(acc[mt][nt], ahi[mt], bl0, bl1);
                    mma16816(acc[mt][nt], alo[mt], bh0, bh1);
                }
            }
        }
    }

#pragma unroll
    for (int mt = 0; mt < 2; mt++) {
        const int r = rowBase + mw * 32 + mt * 16 + g;
#pragma unroll
        for (int nt = 0; nt < 8; nt++) {
            const int c = colBase + nw * 64 + nt * 8 + tg2;
            float bx = 0.f, by = 0.f;
            if (bias) { bx = bias[c]; by = bias[c + 1]; }
            float2 v0 = make_float2(acc[mt][nt][0] + bx, acc[mt][nt][1] + by);
            float2 v1 = make_float2(acc[mt][nt][2] + bx, acc[mt][nt][3] + by);
            *(float2*)(C + (size_t)r * N + c)       = v0;
            *(float2*)(C + (size_t)(r + 8) * N + c) = v1;
        }
    }
}

// ---------------------------------------------------------------------------
// RoPE (in place), unchanged
// ---------------------------------------------------------------------------
__global__ void rope_kernel(float* __restrict__ X, int nheads, int total)
{
    int idx = blockIdx.x * blockDim.x + threadIdx.x;
    if (idx >= total) return;
    const int half = idx & 31;
    const int t = idx >> 5;
    const int head = t % nheads;
    const int row = t / nheads;
    const int pos = row & (SEQ - 1);

    double inv_freq = pow(1000000.0, -(double)half / 32.0);
    double freq = (double)pos * inv_freq;
    float c = (float)cos(freq);
    float s = (float)sin(freq);

    float* base = X + (size_t)row * nheads * HD + head * HD;
    float x1 = base[half];
    float x2 = base[half + 32];
    base[half]      = x1 * c - x2 * s;
    base[half + 32] = x2 * c + x1 * s;
}

// ---------------------------------------------------------------------------
// Tensor-core flash attention (split-bf16, exact softmax weights)
// CTA: 128 q-rows x 1 head; 8 warps, each warp = 16 q-rows x full 128-key stripe.
// K smem: [128 keys][32 words] hi/lo, chunk-XOR swizzled.
// V smem: [64 d][64 words] hi/lo (transposed), chunk-XOR swizzled.
// ---------------------------------------------------------------------------
#define ATTN_SMEM ((128 * 32 * 2 + 64 * 64 * 2) * 4)   // 65536 bytes

__global__ void __launch_bounds__(256) attn_mma_kernel(
    const float* __restrict__ Q, const float* __restrict__ K,
    const float* __restrict__ V, float* __restrict__ O)
{
    extern __shared__ uint32_t sm[];
    uint32_t* Ks_hi = sm;                       // 128*32 words
    uint32_t* Ks_lo = sm + 128 * 32;
    uint32_t* Vs_hi = sm + 2 * 128 * 32;        // 64*64 words
    uint32_t* Vs_lo = sm + 2 * 128 * 32 + 64 * 64;

    const int tid  = threadIdx.x;
    const int lane = tid & 31;
    const int w    = tid >> 5;
    const int g    = lane >> 2;        // 0..7
    const int q4   = lane & 3;         // 0..3
    const int tg2  = q4 * 2;

    const int qt = blockIdx.x;         // 0..15
    const int h  = blockIdx.y;         // 0..31
    const int b  = blockIdx.z;         // 0..1
    const int kvh = h & (KVHEADS - 1);

    const int row0 = qt * 128 + w * 16 + g;     // seq row
    const int row1 = row0 + 8;

    // ---- Q into registers, pre-scaled and hi/lo split (A fragments, 4 k-steps)
    uint32_t qhi[4][4], qlo[4][4];
    {
        const float* Qb = Q + (size_t)(b * SEQ) * D_MODEL + h * HD;
        const float* Qr0 = Qb + (size_t)row0 * D_MODEL;
        const float* Qr1 = Qb + (size_t)row1 * D_MODEL;
#pragma unroll
        for (int ks = 0; ks < 4; ks++) {
            const int d0 = ks * 16 + tg2;
            float2 x0 = *(const float2*)(Qr0 + d0);
            float2 x1 = *(const float2*)(Qr1 + d0);
            float2 x2 = *(const float2*)(Qr0 + d0 + 8);
            float2 x3 = *(const float2*)(Qr1 + d0 + 8);
            const float sc = 0.125f;
            split2(x0.x * sc, x0.y * sc, qhi[ks][0], qlo[ks][0]);
            split2(x1.x * sc, x1.y * sc, qhi[ks][1], qlo[ks][1]);
            split2(x2.x * sc, x2.y * sc, qhi[ks][2], qlo[ks][2]);
            split2(x3.x * sc, x3.y * sc, qhi[ks][3], qlo[ks][3]);
        }
    }

    float o[8][4];
#pragma unroll
    for (int nt = 0; nt < 8; nt++)
#pragma unroll
        for (int j = 0; j < 4; j++) o[nt][j] = 0.0f;
    float m0 = -1e30f, m1 = -1e30f, l0 = 0.0f, l1 = 0.0f;

    const float* Kb = K + (size_t)(b * SEQ) * KVD + kvh * HD;
    const float* Vb = V + (size_t)(b * SEQ) * KVD + kvh * HD;

    for (int kt = 0; kt < SEQ / 128; kt++) {
        __syncthreads();   // previous tile's smem reads done

        // ---- stage K tile: 128 keys x 64 d  (4096 float2)
        {
            const float* Kg = Kb + (size_t)(kt * 128) * KVD;
#pragma unroll
            for (int i = 0; i < 16; i++) {
                const int e   = tid + i * 256;
                const int key = e >> 5;
                const int c2  = e & 31;                 // word index (d/2)
                float2 kv = *(const float2*)(Kg + (size_t)key * KVD + c2 * 2);
                uint32_t hi2, lo2;
                split2(kv.x, kv.y, hi2, lo2);
                const int sw = key * 32 + (c2 ^ ((key & 7) << 2));
                Ks_hi[sw] = hi2;
                Ks_lo[sw] = lo2;
            }
        }
        // ---- stage V tile transposed: Vs[d][key]
        {
            const float* Vg = Vb + (size_t)(kt * 128) * KVD;
            uint16_t* Vh = (uint16_t*)Vs_hi;
            uint16_t* Vl = (uint16_t*)Vs_lo;
#pragma unroll
            for (int i = 0; i < 16; i++) {
                const int e   = tid + i * 256;
                const int key = e >> 5;
                const int c2  = e & 31;
                const int d0  = c2 * 2;
                float2 vv = *(const float2*)(Vg + (size_t)key * KVD + d0);
                __nv_bfloat16 hx = __float2bfloat16(vv.x);
                __nv_bfloat16 lx = __float2bfloat16(vv.x - __bfloat162float(hx));
                __nv_bfloat16 hy = __float2bfloat16(vv.y);
                __nv_bfloat16 ly = __float2bfloat16(vv.y - __bfloat162float(hy));
                const int kw = key >> 1, khalf = key & 1;
                const int w0 = (d0 * 64 + (kw ^ ((d0 & 7) << 2))) * 2 + khalf;
                const int w1 = ((d0 + 1) * 64 + (kw ^ (((d0 + 1) & 7) << 2))) * 2 + khalf;
                Vh[w0] = __bfloat16_as_ushort(hx);
                Vl[w0] = __bfloat16_as_ushort(lx);
                Vh[w1] = __bfloat16_as_ushort(hy);
                Vl[w1] = __bfloat16_as_ushort(ly);
            }
        }
        __syncthreads();

        // ---- S = Q Kt (16 n-tiles of 8 keys), split-bf16 exact
        float sacc[16][4];
#pragma unroll
        for (int nt = 0; nt < 16; nt++)
#pragma unroll
            for (int j = 0; j < 4; j++) sacc[nt][j] = 0.0f;

#pragma unroll
        for (int ks = 0; ks < 4; ks++) {
#pragma unroll
            for (int nt = 0; nt < 16; nt++) {
                const int key = nt * 8 + g;
                const int base = key * 32;
                const int x = (key & 7) << 2;
                uint32_t bh0 = Ks_hi[base + ((ks * 8 + q4) ^ x)];
                uint32_t bh1 = Ks_hi[base + ((ks * 8 + 4 + q4) ^ x)];
                uint32_t bl0 = Ks_lo[base + ((ks * 8 + q4) ^ x)];
                uint32_t bl1 = Ks_lo[base + ((ks * 8 + 4 + q4) ^ x)];
                mma16816(sacc[nt], qhi[ks], bh0, bh1);
                mma16816(sacc[nt], qhi[ks], bl0, bl1);
                mma16816(sacc[nt], qlo[ks], bh0, bh1);
            }
        }

        // ---- online softmax (rows g, g+8 of this warp's 16-row stripe)
        float tmax0 = -1e30f, tmax1 = -1e30f;
#pragma unroll
        for (int nt = 0; nt < 16; nt++) {
            tmax0 = fmaxf(tmax0, fmaxf(sacc[nt][0], sacc[nt][1]));
            tmax1 = fmaxf(tmax1, fmaxf(sacc[nt][2], sacc[nt][3]));
        }
        tmax0 = fmaxf(tmax0, __shfl_xor_sync(0xFFFFFFFF, tmax0, 1));
        tmax0 = fmaxf(tmax0, __shfl_xor_sync(0xFFFFFFFF, tmax0, 2));
        tmax1 = fmaxf(tmax1, __shfl_xor_sync(0xFFFFFFFF, tmax1, 1));
        tmax1 = fmaxf(tmax1, __shfl_xor_sync(0xFFFFFFFF, tmax1, 2));

        const float mn0 = fmaxf(m0, tmax0);
        const float mn1 = fmaxf(m1, tmax1);
        const float sc0 = __expf(m0 - mn0);
        const float sc1 = __expf(m1 - mn1);
        m0 = mn0; m1 = mn1;
        l0 *= sc0; l1 *= sc1;
#pragma unroll
        for (int nt = 0; nt < 8; nt++) {
            o[nt][0] *= sc0; o[nt][1] *= sc0;
            o[nt][2] *= sc1; o[nt][3] *= sc1;
        }

        // ---- P = exp(S - m), packed into PV A-fragments (hi/lo), rowsum into l
        uint32_t pHi[8][4], pLo[8][4];
        float rs0 = 0.0f, rs1 = 0.0f;
#pragma unroll
        for (int t = 0; t < 8; t++) {
            float p00 = __expf(sacc[2 * t][0] - m0);
            float p01 = __expf(sacc[2 * t][1] - m0);
            float p02 = __expf(sacc[2 * t][2] - m1);
            float p03 = __expf(sacc[2 * t][3] - m1);
            float p10 = __expf(sacc[2 * t + 1][0] - m0);
            float p11 = __expf(sacc[2 * t + 1][1] - m0);
            float p12 = __expf(sacc[2 * t + 1][2] - m1);
            float p13 = __expf(sacc[2 * t + 1][3] - m1);
            rs0 += (p00 + p01) + (p10 + p11);
            rs1 += (p02 + p03) + (p12 + p13);
            split2(p00, p01, pHi[t][0], pLo[t][0]);
            split2(p02, p03, pHi[t][1], pLo[t][1]);
            split2(p10, p11, pHi[t][2], pLo[t][2]);
            split2(p12, p13, pHi[t][3], pLo[t][3]);
        }
        rs0 += __shfl_xor_sync(0xFFFFFFFF, rs0, 1);
        rs0 += __shfl_xor_sync(0xFFFFFFFF, rs0, 2);
        rs1 += __shfl_xor_sync(0xFFFFFFFF, rs1, 1);
        rs1 += __shfl_xor_sync(0xFFFFFFFF, rs1, 2);
        l0 += rs0; l1 += rs1;

        // ---- O += P V  (8 k-steps over 128 keys, 8 n-tiles over 64 d)
#pragma unroll
        for (int t = 0; t < 8; t++) {
#pragma unroll
            for (int nt = 0; nt < 8; nt++) {
                const int d = nt * 8 + g;
                const int base = d * 64;
                const int x = (d & 7) << 2;
                uint32_t bh0 = Vs_hi[base + ((t * 8 + q4) ^ x)];
                uint32_t bh1 = Vs_hi[base + ((t * 8 + 4 + q4) ^ x)];
                uint32_t bl0 = Vs_lo[base + ((t * 8 + q4) ^ x)];
                uint32_t bl1 = Vs_lo[base + ((t * 8 + 4 + q4) ^ x)];
                mma16816(o[nt], pHi[t], bh0, bh1);
                mma16816(o[nt], pHi[t], bl0, bl1);
                mma16816(o[nt], pLo[t], bh0, bh1);
            }
        }
    }

    // ---- finalize and write
    const float inv0 = 1.0f / l0;
    const float inv1 = 1.0f / l1;
    float* Ob = O + (size_t)(b * SEQ) * D_MODEL + h * HD;
    float* Or0 = Ob + (size_t)row0 * D_MODEL;
    float* Or1 = Ob + (size_t)row1 * D_MODEL;
#pragma unroll
    for (int nt = 0; nt < 8; nt++) {
        const int c = nt * 8 + tg2;
        *(float2*)(Or0 + c) = make_float2(o[nt][0] * inv0, o[nt][1] * inv0);
        *(float2*)(Or1 + c) = make_float2(o[nt][2] * inv1, o[nt][3] * inv1);
    }
}

// ---------------------------------------------------------------------------
// kernel_launch
// ---------------------------------------------------------------------------
extern "C" void kernel_launch(void* const* d_in, const int* in_sizes, int n_in,
                              void* d_out, int out_size)
{
    const float* q  = (const float*)d_in[0];
    const float* k  = (const float*)d_in[1];
    const float* v  = (const float*)d_in[2];
    const float* Wq = (const float*)d_in[4];
    const float* Wk = (const float*)d_in[5];
    const float* Wv = (const float*)d_in[6];
    const float* Wo = (const float*)d_in[7];
    const float* bo = (const float*)d_in[8];
    float* out = (float*)d_out;

    float *gQ, *gK, *gV, *gAO;
    cudaGetSymbolAddress((void**)&gQ,  g_Q);
    cudaGetSymbolAddress((void**)&gK,  g_K);
    cudaGetSymbolAddress((void**)&gV,  g_V);
    cudaGetSymbolAddress((void**)&gAO, g_AO);

    cudaFuncSetAttribute(attn_mma_kernel, cudaFuncAttributeMaxDynamicSharedMemorySize, ATTN_SMEM);

    // Projections (tensor-core split-bf16)
    mma_gemm_kernel<<<dim3(D_MODEL / 128, NROWS / 128), 256>>>(q, Wq, nullptr, gQ, NROWS, D_MODEL, D_MODEL);
    mma_gemm_kernel<<<dim3(KVD / 128,     NROWS / 128), 256>>>(k, Wk, nullptr, gK, NROWS, KVD, D_MODEL);
    mma_gemm_kernel<<<dim3(KVD / 128,     NROWS / 128), 256>>>(v, Wv, nullptr, gV, NROWS, KVD, D_MODEL);

    // RoPE on Q and K (in place)
    {
        int totQ = NROWS * QHEADS * 32;
        rope_kernel<<<(totQ + 255) / 256, 256>>>(gQ, QHEADS, totQ);
        int totK = NROWS * KVHEADS * 32;
        rope_kernel<<<(totK + 255) / 256, 256>>>(gK, KVHEADS, totK);
    }

    // Attention (tensor-core flash, split-bf16)
    attn_mma_kernel<<<dim3(SEQ / 128, QHEADS, BATCH), 256, ATTN_SMEM>>>(gQ, gK, gV, gAO);

    // Output projection + bias (tensor-core split-bf16)
    mma_gemm_kernel<<<dim3(D_MODEL / 128, NROWS / 128), 256>>>(gAO, Wo, bo, out, NROWS, D_MODEL, D_MODEL);
}

// round 5
// speedup vs baseline: 2.9482x; 1.3885x over previous
#include <cuda_runtime.h>
#include <cuda_bf16.h>
#include <math.h>
#include <stdint.h>

// Problem constants
#define D_MODEL 2048
#define QHEADS  32
#define KVHEADS 8
#define HD      64
#define BATCH   2
#define SEQ     2048
#define NROWS   (BATCH * SEQ)      // 4096
#define KVD     (KVHEADS * HD)     // 512

// ---------------------------------------------------------------------------
// Scratch (static device globals)
// ---------------------------------------------------------------------------
__device__ float g_Q[(size_t)NROWS * D_MODEL];
__device__ float g_K[(size_t)NROWS * KVD];
__device__ float g_V[(size_t)NROWS * KVD];
__device__ float g_AO[(size_t)NROWS * D_MODEL];
__device__ uint16_t g_Ahi[(size_t)NROWS * D_MODEL];
__device__ uint16_t g_Alo[(size_t)NROWS * D_MODEL];
__device__ uint16_t g_Bhi[(size_t)D_MODEL * D_MODEL];   // n-major [N][K]
__device__ uint16_t g_Blo[(size_t)D_MODEL * D_MODEL];
__device__ float g_cosT[SEQ * 32];
__device__ float g_sinT[SEQ * 32];

// ---------------------------------------------------------------------------
// Helpers
// ---------------------------------------------------------------------------
__device__ __forceinline__ uint32_t smem_u32(const void* p) {
    uint32_t a;
    asm("{ .reg .u64 t; cvta.to.shared.u64 t, %1; cvt.u32.u64 %0, t; }" : "=r"(a) : "l"(p));
    return a;
}

__device__ __forceinline__ void mma16816(float* c, const uint32_t* a, uint32_t b0, uint32_t b1) {
    asm volatile(
        "mma.sync.aligned.m16n8k16.row.col.f32.bf16.bf16.f32 "
        "{%0,%1,%2,%3}, {%4,%5,%6,%7}, {%8,%9}, {%0,%1,%2,%3};"
        : "+f"(c[0]), "+f"(c[1]), "+f"(c[2]), "+f"(c[3])
        : "r"(a[0]), "r"(a[1]), "r"(a[2]), "r"(a[3]), "r"(b0), "r"(b1));
}

// pack (x -> lo half, y -> hi half) with hi/lo fp32 split
__device__ __forceinline__ void split2(float x, float y, uint32_t& hi, uint32_t& lo) {
    asm("cvt.rn.bf16x2.f32 %0, %1, %2;" : "=r"(hi) : "f"(y), "f"(x));
    float hx = __uint_as_float(hi << 16);
    float hy = __uint_as_float(hi & 0xFFFF0000u);
    asm("cvt.rn.bf16x2.f32 %0, %1, %2;" : "=r"(lo) : "f"(y - hy), "f"(x - hx));
}

#define LDMX4(R, A) asm volatile( \
    "ldmatrix.sync.aligned.m8n8.x4.shared.b16 {%0,%1,%2,%3}, [%4];" \
    : "=r"((R)[0]), "=r"((R)[1]), "=r"((R)[2]), "=r"((R)[3]) : "r"(A))

#define CP_ASYNC16(dst, src) asm volatile( \
    "cp.async.cg.shared.global [%0], [%1], 16;" :: "r"(dst), "l"(src) : "memory")
#define CP_COMMIT() asm volatile("cp.async.commit_group;" ::: "memory")
#define CP_WAIT2()  asm volatile("cp.async.wait_group 2;" ::: "memory")

// ---------------------------------------------------------------------------
// Pre-split conversion kernels
// ---------------------------------------------------------------------------
__global__ void convA_kernel(const float* __restrict__ X, uint16_t* __restrict__ hi,
                             uint16_t* __restrict__ lo, int total2)
{
    int idx = blockIdx.x * blockDim.x + threadIdx.x;
    if (idx >= total2) return;
    float2 a = *(const float2*)(X + (size_t)idx * 2);
    uint32_t h, l;
    split2(a.x, a.y, h, l);
    *(uint32_t*)(hi + (size_t)idx * 2) = h;
    *(uint32_t*)(lo + (size_t)idx * 2) = l;
}

// B [K][N] row-major -> Bt hi/lo [N][K] (n-major), 32x32 smem transpose tiles
__global__ void __launch_bounds__(256) convB_kernel(
    const float* __restrict__ B, uint16_t* __restrict__ hi,
    uint16_t* __restrict__ lo, int N, int K)
{
    __shared__ float s[32][33];
    const int n0 = blockIdx.x * 32, k0 = blockIdx.y * 32;
    const int tid = threadIdx.x;
#pragma unroll
    for (int i = 0; i < 4; i++) {
        int e = tid + i * 256;
        int k = e >> 5, n = e & 31;
        s[k][n] = B[(size_t)(k0 + k) * N + n0 + n];
    }
    __syncthreads();
#pragma unroll
    for (int i = 0; i < 2; i++) {
        int o = tid + i * 256;           // 0..511
        int pc = o & 15, r = o >> 4;     // pc: k-pair, r: n within tile
        int k2 = pc * 2;
        uint32_t h, l;
        split2(s[k2][r], s[k2 + 1][r], h, l);
        *(uint32_t*)(hi + (size_t)(n0 + r) * K + k0 + k2) = h;
        *(uint32_t*)(lo + (size_t)(n0 + r) * K + k0 + k2) = l;
    }
}

// ---------------------------------------------------------------------------
// Split-bf16 tensor-core GEMM (pre-split inputs, cp.async 3-stage, ldmatrix)
// C[M,N] = A[M,K] @ B[K,N] (+bias). Block 128x128, BK=32, 8 warps (4m x 2n).
// smem row layout per (row, chunk): [hi 64B | lo 64B], chunk-swizzled (^row&7).
// ---------------------------------------------------------------------------
#define GSTAGES 3
#define GSTAGE_BYTES 32768
#define GEMM_SMEM (GSTAGES * GSTAGE_BYTES)    // 98304

__global__ void __launch_bounds__(256) mma_gemm_kernel(
    const uint16_t* __restrict__ Ahi, const uint16_t* __restrict__ Alo,
    const uint16_t* __restrict__ Bhi, const uint16_t* __restrict__ Blo,
    const float* __restrict__ bias, float* __restrict__ C,
    int M, int N, int K)
{
    extern __shared__ __align__(128) char gsm[];
    const int tid  = threadIdx.x;
    const int lane = tid & 31;
    const int w    = tid >> 5;
    const int mw   = w >> 1;
    const int nw   = w & 1;
    const int rowBase = blockIdx.y * 128;
    const int colBase = blockIdx.x * 128;
    const uint32_t smemBase = smem_u32(gsm);
    const int nChunks = K >> 5;

    float acc[2][8][4];
#pragma unroll
    for (int mt = 0; mt < 2; mt++)
#pragma unroll
        for (int nt = 0; nt < 8; nt++)
#pragma unroll
            for (int j = 0; j < 4; j++) acc[mt][nt][j] = 0.0f;

    auto prefetch = [&](int ch, int stage) {
        if (ch < nChunks) {
            const uint32_t sA = smemBase + stage * GSTAGE_BYTES;
            const uint32_t sB = sA + 16384;
#pragma unroll
            for (int i = 0; i < 8; i++) {
                const int flat = i * 256 + tid;       // 0..2047
                const int isB  = flat >> 10;          // i<4 -> A, else B
                const int f    = flat & 1023;
                const int r    = f >> 3, c = f & 7;
                const uint16_t* hp = isB ? Bhi : Ahi;
                const uint16_t* lp = isB ? Blo : Alo;
                const int grow = (isB ? colBase : rowBase) + r;
                const uint16_t* src = ((c < 4) ? hp : lp) + (size_t)grow * K + ch * 32 + (c & 3) * 8;
                const uint32_t dst = (isB ? sB : sA) + r * 128 + ((c ^ (r & 7)) << 4);
                CP_ASYNC16(dst, src);
            }
        }
        CP_COMMIT();
    };

    prefetch(0, 0);
    prefetch(1, 1);
    prefetch(2, 2);

    for (int ch = 0; ch < nChunks; ch++) {
        CP_WAIT2();
        __syncthreads();
        const int stage = ch % GSTAGES;
        const uint32_t sA = smemBase + stage * GSTAGE_BYTES;
        const uint32_t sB = sA + 16384;

#pragma unroll
        for (int ks = 0; ks < 2; ks++) {
            uint32_t ahi[2][4], alo[2][4];
#pragma unroll
            for (int mt = 0; mt < 2; mt++) {
                const int r  = mw * 32 + mt * 16 + (lane & 7) + ((lane >> 3) & 1) * 8;
                const int cb = ks * 2 + (lane >> 4);
                const uint32_t rowA = sA + r * 128;
                LDMX4(ahi[mt], rowA + ((cb ^ (r & 7)) << 4));
                LDMX4(alo[mt], rowA + (((cb + 4) ^ (r & 7)) << 4));
            }
#pragma unroll
            for (int ntp = 0; ntp < 4; ntp++) {
                const int n  = nw * 64 + ntp * 16 + (lane & 7) + ((lane >> 4) << 3);
                const int cb = ks * 2 + ((lane >> 3) & 1);
                const uint32_t rowB = sB + n * 128;
                uint32_t bh[4], bl[4];
                LDMX4(bh, rowB + ((cb ^ (n & 7)) << 4));
                LDMX4(bl, rowB + (((cb + 4) ^ (n & 7)) << 4));
#pragma unroll
                for (int mt = 0; mt < 2; mt++) {
                    mma16816(acc[mt][2 * ntp],     ahi[mt], bh[0], bh[1]);
                    mma16816(acc[mt][2 * ntp],     ahi[mt], bl[0], bl[1]);
                    mma16816(acc[mt][2 * ntp],     alo[mt], bh[0], bh[1]);
                    mma16816(acc[mt][2 * ntp + 1], ahi[mt], bh[2], bh[3]);
                    mma16816(acc[mt][2 * ntp + 1], ahi[mt], bl[2], bl[3]);
                    mma16816(acc[mt][2 * ntp + 1], alo[mt], bh[2], bh[3]);
                }
            }
        }
        __syncthreads();
        prefetch(ch + GSTAGES, stage);
    }

    // ---- epilogue
    const int g   = lane >> 2;
    const int tg2 = (lane & 3) * 2;
#pragma unroll
    for (int mt = 0; mt < 2; mt++) {
        const int r = rowBase + mw * 32 + mt * 16 + g;
#pragma unroll
        for (int nt = 0; nt < 8; nt++) {
            const int c = colBase + nw * 64 + nt * 8 + tg2;
            float bx = 0.f, by = 0.f;
            if (bias) { bx = bias[c]; by = bias[c + 1]; }
            *(float2*)(C + (size_t)r * N + c)       = make_float2(acc[mt][nt][0] + bx, acc[mt][nt][1] + by);
            *(float2*)(C + (size_t)(r + 8) * N + c) = make_float2(acc[mt][nt][2] + bx, acc[mt][nt][3] + by);
        }
    }
}

// ---------------------------------------------------------------------------
// RoPE: table (double-precision phases, computed once) + cheap apply kernel
// ---------------------------------------------------------------------------
__global__ void rope_table_kernel()
{
    int idx = blockIdx.x * blockDim.x + threadIdx.x;   // SEQ*32 = 65536
    int half = idx & 31, pos = idx >> 5;
    double inv_freq = pow(1000000.0, -(double)half / 32.0);
    double f = (double)pos * inv_freq;
    g_cosT[idx] = (float)cos(f);
    g_sinT[idx] = (float)sin(f);
}

__global__ void rope_kernel(float* __restrict__ X, int nheads, int total)
{
    int idx = blockIdx.x * blockDim.x + threadIdx.x;
    if (idx >= total) return;
    const int half = idx & 31;
    const int t = idx >> 5;
    const int head = t % nheads;
    const int row = t / nheads;
    const int pos = row & (SEQ - 1);

    const float c = g_cosT[(pos << 5) + half];
    const float s = g_sinT[(pos << 5) + half];

    float* base = X + (size_t)row * nheads * HD + head * HD;
    float x1 = base[half];
    float x2 = base[half + 32];
    base[half]      = x1 * c - x2 * s;
    base[half + 32] = x2 * c + x1 * s;
}

// ---------------------------------------------------------------------------
// Tensor-core flash attention (unchanged from R4)
// ---------------------------------------------------------------------------
#define ATTN_SMEM ((128 * 32 * 2 + 64 * 64 * 2) * 4)   // 65536 bytes

__global__ void __launch_bounds__(256) attn_mma_kernel(
    const float* __restrict__ Q, const float* __restrict__ K,
    const float* __restrict__ V, float* __restrict__ O)
{
    extern __shared__ uint32_t sm[];
    uint32_t* Ks_hi = sm;
    uint32_t* Ks_lo = sm + 128 * 32;
    uint32_t* Vs_hi = sm + 2 * 128 * 32;
    uint32_t* Vs_lo = sm + 2 * 128 * 32 + 64 * 64;

    const int tid  = threadIdx.x;
    const int lane = tid & 31;
    const int w    = tid >> 5;
    const int g    = lane >> 2;
    const int q4   = lane & 3;
    const int tg2  = q4 * 2;

    const int qt = blockIdx.x;
    const int h  = blockIdx.y;
    const int b  = blockIdx.z;
    const int kvh = h & (KVHEADS - 1);

    const int row0 = qt * 128 + w * 16 + g;
    const int row1 = row0 + 8;

    uint32_t qhi[4][4], qlo[4][4];
    {
        const float* Qb = Q + (size_t)(b * SEQ) * D_MODEL + h * HD;
        const float* Qr0 = Qb + (size_t)row0 * D_MODEL;
        const float* Qr1 = Qb + (size_t)row1 * D_MODEL;
#pragma unroll
        for (int ks = 0; ks < 4; ks++) {
            const int d0 = ks * 16 + tg2;
            float2 x0 = *(const float2*)(Qr0 + d0);
            float2 x1 = *(const float2*)(Qr1 + d0);
            float2 x2 = *(const float2*)(Qr0 + d0 + 8);
            float2 x3 = *(const float2*)(Qr1 + d0 + 8);
            const float sc = 0.125f;
            split2(x0.x * sc, x0.y * sc, qhi[ks][0], qlo[ks][0]);
            split2(x1.x * sc, x1.y * sc, qhi[ks][1], qlo[ks][1]);
            split2(x2.x * sc, x2.y * sc, qhi[ks][2], qlo[ks][2]);
            split2(x3.x * sc, x3.y * sc, qhi[ks][3], qlo[ks][3]);
        }
    }

    float o[8][4];
#pragma unroll
    for (int nt = 0; nt < 8; nt++)
#pragma unroll
        for (int j = 0; j < 4; j++) o[nt][j] = 0.0f;
    float m0 = -1e30f, m1 = -1e30f, l0 = 0.0f, l1 = 0.0f;

    const float* Kb = K + (size_t)(b * SEQ) * KVD + kvh * HD;
    const float* Vb = V + (size_t)(b * SEQ) * KVD + kvh * HD;

    for (int kt = 0; kt < SEQ / 128; kt++) {
        __syncthreads();

        {
            const float* Kg = Kb + (size_t)(kt * 128) * KVD;
#pragma unroll
            for (int i = 0; i < 16; i++) {
                const int e   = tid + i * 256;
                const int key = e >> 5;
                const int c2  = e & 31;
                float2 kv = *(const float2*)(Kg + (size_t)key * KVD + c2 * 2);
                uint32_t hi2, lo2;
                split2(kv.x, kv.y, hi2, lo2);
                const int sw = key * 32 + (c2 ^ ((key & 7) << 2));
                Ks_hi[sw] = hi2;
                Ks_lo[sw] = lo2;
            }
        }
        {
            const float* Vg = Vb + (size_t)(kt * 128) * KVD;
            uint16_t* Vh = (uint16_t*)Vs_hi;
            uint16_t* Vl = (uint16_t*)Vs_lo;
#pragma unroll
            for (int i = 0; i < 16; i++) {
                const int e   = tid + i * 256;
                const int key = e >> 5;
                const int c2  = e & 31;
                const int d0  = c2 * 2;
                float2 vv = *(const float2*)(Vg + (size_t)key * KVD + d0);
                __nv_bfloat16 hx = __float2bfloat16(vv.x);
                __nv_bfloat16 lx = __float2bfloat16(vv.x - __bfloat162float(hx));
                __nv_bfloat16 hy = __float2bfloat16(vv.y);
                __nv_bfloat16 ly = __float2bfloat16(vv.y - __bfloat162float(hy));
                const int kw = key >> 1, khalf = key & 1;
                const int w0 = (d0 * 64 + (kw ^ ((d0 & 7) << 2))) * 2 + khalf;
                const int w1 = ((d0 + 1) * 64 + (kw ^ (((d0 + 1) & 7) << 2))) * 2 + khalf;
                Vh[w0] = __bfloat16_as_ushort(hx);
                Vl[w0] = __bfloat16_as_ushort(lx);
                Vh[w1] = __bfloat16_as_ushort(hy);
                Vl[w1] = __bfloat16_as_ushort(ly);
            }
        }
        __syncthreads();

        float sacc[16][4];
#pragma unroll
        for (int nt = 0; nt < 16; nt++)
#pragma unroll
            for (int j = 0; j < 4; j++) sacc[nt][j] = 0.0f;

#pragma unroll
        for (int ks = 0; ks < 4; ks++) {
#pragma unroll
            for (int nt = 0; nt < 16; nt++) {
                const int key = nt * 8 + g;
                const int base = key * 32;
                const int x = (key & 7) << 2;
                uint32_t bh0 = Ks_hi[base + ((ks * 8 + q4) ^ x)];
                uint32_t bh1 = Ks_hi[base + ((ks * 8 + 4 + q4) ^ x)];
                uint32_t bl0 = Ks_lo[base + ((ks * 8 + q4) ^ x)];
                uint32_t bl1 = Ks_lo[base + ((ks * 8 + 4 + q4) ^ x)];
                mma16816(sacc[nt], qhi[ks], bh0, bh1);
                mma16816(sacc[nt], qhi[ks], bl0, bl1);
                mma16816(sacc[nt], qlo[ks], bh0, bh1);
            }
        }

        float tmax0 = -1e30f, tmax1 = -1e30f;
#pragma unroll
        for (int nt = 0; nt < 16; nt++) {
            tmax0 = fmaxf(tmax0, fmaxf(sacc[nt][0], sacc[nt][1]));
            tmax1 = fmaxf(tmax1, fmaxf(sacc[nt][2], sacc[nt][3]));
        }
        tmax0 = fmaxf(tmax0, __shfl_xor_sync(0xFFFFFFFF, tmax0, 1));
        tmax0 = fmaxf(tmax0, __shfl_xor_sync(0xFFFFFFFF, tmax0, 2));
        tmax1 = fmaxf(tmax1, __shfl_xor_sync(0xFFFFFFFF, tmax1, 1));
        tmax1 = fmaxf(tmax1, __shfl_xor_sync(0xFFFFFFFF, tmax1, 2));

        const float mn0 = fmaxf(m0, tmax0);
        const float mn1 = fmaxf(m1, tmax1);
        const float sc0 = __expf(m0 - mn0);
        const float sc1 = __expf(m1 - mn1);
        m0 = mn0; m1 = mn1;
        l0 *= sc0; l1 *= sc1;
#pragma unroll
        for (int nt = 0; nt < 8; nt++) {
            o[nt][0] *= sc0; o[nt][1] *= sc0;
            o[nt][2] *= sc1; o[nt][3] *= sc1;
        }

        uint32_t pHi[8][4], pLo[8][4];
        float rs0 = 0.0f, rs1 = 0.0f;
#pragma unroll
        for (int t = 0; t < 8; t++) {
            float p00 = __expf(sacc[2 * t][0] - m0);
            float p01 = __expf(sacc[2 * t][1] - m0);
            float p02 = __expf(sacc[2 * t][2] - m1);
            float p03 = __expf(sacc[2 * t][3] - m1);
            float p10 = __expf(sacc[2 * t + 1][0] - m0);
            float p11 = __expf(sacc[2 * t + 1][1] - m0);
            float p12 = __expf(sacc[2 * t + 1][2] - m1);
            float p13 = __expf(sacc[2 * t + 1][3] - m1);
            rs0 += (p00 + p01) + (p10 + p11);
            rs1 += (p02 + p03) + (p12 + p13);
            split2(p00, p01, pHi[t][0], pLo[t][0]);
            split2(p02, p03, pHi[t][1], pLo[t][1]);
            split2(p10, p11, pHi[t][2], pLo[t][2]);
            split2(p12, p13, pHi[t][3], pLo[t][3]);
        }
        rs0 += __shfl_xor_sync(0xFFFFFFFF, rs0, 1);
        rs0 += __shfl_xor_sync(0xFFFFFFFF, rs0, 2);
        rs1 += __shfl_xor_sync(0xFFFFFFFF, rs1, 1);
        rs1 += __shfl_xor_sync(0xFFFFFFFF, rs1, 2);
        l0 += rs0; l1 += rs1;

#pragma unroll
        for (int t = 0; t < 8; t++) {
#pragma unroll
            for (int nt = 0; nt < 8; nt++) {
                const int d = nt * 8 + g;
                const int base = d * 64;
                const int x = (d & 7) << 2;
                uint32_t bh0 = Vs_hi[base + ((t * 8 + q4) ^ x)];
                uint32_t bh1 = Vs_hi[base + ((t * 8 + 4 + q4) ^ x)];
                uint32_t bl0 = Vs_lo[base + ((t * 8 + q4) ^ x)];
                uint32_t bl1 = Vs_lo[base + ((t * 8 + 4 + q4) ^ x)];
                mma16816(o[nt], pHi[t], bh0, bh1);
                mma16816(o[nt], pHi[t], bl0, bl1);
                mma16816(o[nt], pLo[t], bh0, bh1);
            }
        }
    }

    const float inv0 = 1.0f / l0;
    const float inv1 = 1.0f / l1;
    float* Ob = O + (size_t)(b * SEQ) * D_MODEL + h * HD;
    float* Or0 = Ob + (size_t)row0 * D_MODEL;
    float* Or1 = Ob + (size_t)row1 * D_MODEL;
#pragma unroll
    for (int nt = 0; nt < 8; nt++) {
        const int c = nt * 8 + tg2;
        *(float2*)(Or0 + c) = make_float2(o[nt][0] * inv0, o[nt][1] * inv0);
        *(float2*)(Or1 + c) = make_float2(o[nt][2] * inv1, o[nt][3] * inv1);
    }
}

// ---------------------------------------------------------------------------
// kernel_launch
// ---------------------------------------------------------------------------
extern "C" void kernel_launch(void* const* d_in, const int* in_sizes, int n_in,
                              void* d_out, int out_size)
{
    const float* q  = (const float*)d_in[0];
    const float* k  = (const float*)d_in[1];
    const float* v  = (const float*)d_in[2];
    const float* Wq = (const float*)d_in[4];
    const float* Wk = (const float*)d_in[5];
    const float* Wv = (const float*)d_in[6];
    const float* Wo = (const float*)d_in[7];
    const float* bo = (const float*)d_in[8];
    float* out = (float*)d_out;

    float *gQ, *gK, *gV, *gAO;
    uint16_t *gAhi, *gAlo, *gBhi, *gBlo;
    cudaGetSymbolAddress((void**)&gQ,   g_Q);
    cudaGetSymbolAddress((void**)&gK,   g_K);
    cudaGetSymbolAddress((void**)&gV,   g_V);
    cudaGetSymbolAddress((void**)&gAO,  g_AO);
    cudaGetSymbolAddress((void**)&gAhi, g_Ahi);
    cudaGetSymbolAddress((void**)&gAlo, g_Alo);
    cudaGetSymbolAddress((void**)&gBhi, g_Bhi);
    cudaGetSymbolAddress((void**)&gBlo, g_Blo);

    cudaFuncSetAttribute(mma_gemm_kernel, cudaFuncAttributeMaxDynamicSharedMemorySize, GEMM_SMEM);
    cudaFuncSetAttribute(attn_mma_kernel, cudaFuncAttributeMaxDynamicSharedMemorySize, ATTN_SMEM);

    const int totA2 = NROWS * D_MODEL / 2;   // float2 count for A-side conversions

    // RoPE table (independent; launch first)
    rope_table_kernel<<<SEQ * 32 / 256, 256>>>();

    // Q projection
    convB_kernel<<<dim3(D_MODEL / 32, D_MODEL / 32), 256>>>(Wq, gBhi, gBlo, D_MODEL, D_MODEL);
    convA_kernel<<<totA2 / 256, 256>>>(q, gAhi, gAlo, totA2);
    mma_gemm_kernel<<<dim3(D_MODEL / 128, NROWS / 128), 256, GEMM_SMEM>>>(
        gAhi, gAlo, gBhi, gBlo, nullptr, gQ, NROWS, D_MODEL, D_MODEL);

    // K projection
    convB_kernel<<<dim3(KVD / 32, D_MODEL / 32), 256>>>(Wk, gBhi, gBlo, KVD, D_MODEL);
    convA_kernel<<<totA2 / 256, 256>>>(k, gAhi, gAlo, totA2);
    mma_gemm_kernel<<<dim3(KVD / 128, NROWS / 128), 256, GEMM_SMEM>>>(
        gAhi, gAlo, gBhi, gBlo, nullptr, gK, NROWS, KVD, D_MODEL);

    // V projection
    convB_kernel<<<dim3(KVD / 32, D_MODEL / 32), 256>>>(Wv, gBhi, gBlo, KVD, D_MODEL);
    convA_kernel<<<totA2 / 256, 256>>>(v, gAhi, gAlo, totA2);
    mma_gemm_kernel<<<dim3(KVD / 128, NROWS / 128), 256, GEMM_SMEM>>>(
        gAhi, gAlo, gBhi, gBlo, nullptr, gV, NROWS, KVD, D_MODEL);

    // RoPE
    {
        int totQ = NROWS * QHEADS * 32;
        rope_kernel<<<(totQ + 255) / 256, 256>>>(gQ, QHEADS, totQ);
        int totK = NROWS * KVHEADS * 32;
        rope_kernel<<<(totK + 255) / 256, 256>>>(gK, KVHEADS, totK);
    }

    // Attention
    attn_mma_kernel<<<dim3(SEQ / 128, QHEADS, BATCH), 256, ATTN_SMEM>>>(gQ, gK, gV, gAO);

    // Output projection + bias
    convB_kernel<<<dim3(D_MODEL / 32, D_MODEL / 32), 256>>>(Wo, gBhi, gBlo, D_MODEL, D_MODEL);
    convA_kernel<<<totA2 / 256, 256>>>(gAO, gAhi, gAlo, totA2);
    mma_gemm_kernel<<<dim3(D_MODEL / 128, NROWS / 128), 256, GEMM_SMEM>>>(
        gAhi, gAlo, gBhi, gBlo, bo, out, NROWS, D_MODEL, D_MODEL);
}

// round 6
// speedup vs baseline: 3.6946x; 1.2532x over previous
#include <cuda_runtime.h>
#include <cuda_bf16.h>
#include <math.h>
#include <stdint.h>

// Problem constants
#define D_MODEL 2048
#define QHEADS  32
#define KVHEADS 8
#define HD      64
#define BATCH   2
#define SEQ     2048
#define NROWS   (BATCH * SEQ)      // 4096
#define KVD     (KVHEADS * HD)     // 512

// ---------------------------------------------------------------------------
// Scratch (static device globals)
// ---------------------------------------------------------------------------
__device__ float g_Q[(size_t)NROWS * D_MODEL];
__device__ float g_K[(size_t)NROWS * KVD];
__device__ float g_V[(size_t)NROWS * KVD];
__device__ float g_AO[(size_t)NROWS * D_MODEL];
__device__ uint16_t g_Ahi[(size_t)NROWS * D_MODEL];
__device__ uint16_t g_Alo[(size_t)NROWS * D_MODEL];
__device__ uint16_t g_Bhi[(size_t)D_MODEL * D_MODEL];   // n-major [N][K]
__device__ uint16_t g_Blo[(size_t)D_MODEL * D_MODEL];
// pre-split, roped K: [b][kvh][key][d] bf16 hi/lo
__device__ uint16_t g_Khi[(size_t)BATCH * KVHEADS * SEQ * HD];
__device__ uint16_t g_Klo[(size_t)BATCH * KVHEADS * SEQ * HD];
// pre-split, transposed V: [b][kvh][d][key] bf16 hi/lo
__device__ uint16_t g_Vhi[(size_t)BATCH * KVHEADS * HD * SEQ];
__device__ uint16_t g_Vlo[(size_t)BATCH * KVHEADS * HD * SEQ];
__device__ float g_cosT[SEQ * 32];
__device__ float g_sinT[SEQ * 32];

// ---------------------------------------------------------------------------
// Helpers
// ---------------------------------------------------------------------------
__device__ __forceinline__ uint32_t smem_u32(const void* p) {
    uint32_t a;
    asm("{ .reg .u64 t; cvta.to.shared.u64 t, %1; cvt.u32.u64 %0, t; }" : "=r"(a) : "l"(p));
    return a;
}

__device__ __forceinline__ void mma16816(float* c, const uint32_t* a, uint32_t b0, uint32_t b1) {
    asm volatile(
        "mma.sync.aligned.m16n8k16.row.col.f32.bf16.bf16.f32 "
        "{%0,%1,%2,%3}, {%4,%5,%6,%7}, {%8,%9}, {%0,%1,%2,%3};"
        : "+f"(c[0]), "+f"(c[1]), "+f"(c[2]), "+f"(c[3])
        : "r"(a[0]), "r"(a[1]), "r"(a[2]), "r"(a[3]), "r"(b0), "r"(b1));
}

// pack (x -> lo half, y -> hi half) with hi/lo fp32 split
__device__ __forceinline__ void split2(float x, float y, uint32_t& hi, uint32_t& lo) {
    asm("cvt.rn.bf16x2.f32 %0, %1, %2;" : "=r"(hi) : "f"(y), "f"(x));
    float hx = __uint_as_float(hi << 16);
    float hy = __uint_as_float(hi & 0xFFFF0000u);
    asm("cvt.rn.bf16x2.f32 %0, %1, %2;" : "=r"(lo) : "f"(y - hy), "f"(x - hx));
}

#define LDMX4(R, A) asm volatile( \
    "ldmatrix.sync.aligned.m8n8.x4.shared.b16 {%0,%1,%2,%3}, [%4];" \
    : "=r"((R)[0]), "=r"((R)[1]), "=r"((R)[2]), "=r"((R)[3]) : "r"(A))

#define CP_ASYNC16(dst, src) asm volatile( \
    "cp.async.cg.shared.global [%0], [%1], 16;" :: "r"(dst), "l"(src) : "memory")
#define CP_COMMIT() asm volatile("cp.async.commit_group;" ::: "memory")
#define CP_WAIT2()  asm volatile("cp.async.wait_group 2;" ::: "memory")
#define CP_WAIT1()  asm volatile("cp.async.wait_group 1;" ::: "memory")

// ---------------------------------------------------------------------------
// RoPE phase table (computed once per graph replay; double precision)
// ---------------------------------------------------------------------------
__global__ void rope_table_kernel()
{
    int idx = blockIdx.x * blockDim.x + threadIdx.x;   // SEQ*32
    int half = idx & 31, pos = idx >> 5;
    double inv_freq = pow(1000000.0, -(double)half / 32.0);
    double f = (double)pos * inv_freq;
    g_cosT[idx] = (float)cos(f);
    g_sinT[idx] = (float)sin(f);
}

// ---------------------------------------------------------------------------
// Pre-split conversion kernels (GEMM inputs)
// ---------------------------------------------------------------------------
__global__ void convA_kernel(const float* __restrict__ X, uint16_t* __restrict__ hi,
                             uint16_t* __restrict__ lo, int total2)
{
    int idx = blockIdx.x * blockDim.x + threadIdx.x;
    if (idx >= total2) return;
    float2 a = *(const float2*)(X + (size_t)idx * 2);
    uint32_t h, l;
    split2(a.x, a.y, h, l);
    *(uint32_t*)(hi + (size_t)idx * 2) = h;
    *(uint32_t*)(lo + (size_t)idx * 2) = l;
}

// B [K][N] row-major -> Bt hi/lo [N][K] (n-major), 32x32 smem transpose tiles
__global__ void __launch_bounds__(256) convB_kernel(
    const float* __restrict__ B, uint16_t* __restrict__ hi,
    uint16_t* __restrict__ lo, int N, int K)
{
    __shared__ float s[32][33];
    const int n0 = blockIdx.x * 32, k0 = blockIdx.y * 32;
    const int tid = threadIdx.x;
#pragma unroll
    for (int i = 0; i < 4; i++) {
        int e = tid + i * 256;
        int k = e >> 5, n = e & 31;
        s[k][n] = B[(size_t)(k0 + k) * N + n0 + n];
    }
    __syncthreads();
#pragma unroll
    for (int i = 0; i < 2; i++) {
        int o = tid + i * 256;
        int pc = o & 15, r = o >> 4;
        int k2 = pc * 2;
        uint32_t h, l;
        split2(s[k2][r], s[k2 + 1][r], h, l);
        *(uint32_t*)(hi + (size_t)(n0 + r) * K + k0 + k2) = h;
        *(uint32_t*)(lo + (size_t)(n0 + r) * K + k0 + k2) = l;
    }
}

// ---------------------------------------------------------------------------
// convK: rope + split K projection -> [b][kvh][key][d] bf16 hi/lo
// ---------------------------------------------------------------------------
__global__ void convK_kernel(const float* __restrict__ Kin,
                             uint16_t* __restrict__ hi, uint16_t* __restrict__ lo)
{
    int idx = blockIdx.x * blockDim.x + threadIdx.x;   // NROWS * 256
    int r = idx & 255;
    int row = idx >> 8;
    int kvh = r >> 5, d2 = r & 31;
    int d = d2 * 2;
    int pos = row & (SEQ - 1);
    int b = row >> 11;

    const float* base = Kin + (size_t)row * KVD + kvh * HD;
    float2 x = *(const float2*)(base + d);
    float2 p = *(const float2*)(base + ((d < 32) ? d + 32 : d - 32));
    const float* cp = g_cosT + (pos << 5);
    const float* sp = g_sinT + (pos << 5);
    int hb = d & 31;
    float c0 = cp[hb], s0 = sp[hb], c1 = cp[hb + 1], s1 = sp[hb + 1];
    float rx, ry;
    if (d < 32) { rx = x.x * c0 - p.x * s0; ry = x.y * c1 - p.y * s1; }
    else        { rx = x.x * c0 + p.x * s0; ry = x.y * c1 + p.y * s1; }
    uint32_t h, l;
    split2(rx, ry, h, l);
    size_t o = ((size_t)((b * KVHEADS + kvh) * SEQ + pos)) * 32 + d2;   // u32 units
    ((uint32_t*)hi)[o] = h;
    ((uint32_t*)lo)[o] = l;
}

// ---------------------------------------------------------------------------
// convV: split + transpose V projection -> [b][kvh][d][key] bf16 hi/lo
// one block per 64-key slab per (b,kvh)
// ---------------------------------------------------------------------------
__global__ void __launch_bounds__(256) convV_kernel(const float* __restrict__ Vin,
                                                    uint16_t* __restrict__ hi,
                                                    uint16_t* __restrict__ lo)
{
    __shared__ uint16_t hiT[64][66];
    __shared__ uint16_t loT[64][66];
    const int k0 = blockIdx.x * 64;
    const int bk = blockIdx.y;                 // b*KVHEADS + kvh
    const int b = bk >> 3, kvh = bk & 7;
    const int tid = threadIdx.x;

#pragma unroll
    for (int i = 0; i < 8; i++) {
        int e = tid + i * 256;                 // 2048 float2
        int kt = e >> 5, d2 = e & 31;
        float2 v = *(const float2*)(Vin + (size_t)(b * SEQ + k0 + kt) * KVD + kvh * HD + d2 * 2);
        uint32_t h, l;
        split2(v.x, v.y, h, l);
        hiT[d2 * 2][kt]     = (uint16_t)(h & 0xFFFF);
        hiT[d2 * 2 + 1][kt] = (uint16_t)(h >> 16);
        loT[d2 * 2][kt]     = (uint16_t)(l & 0xFFFF);
        loT[d2 * 2 + 1][kt] = (uint16_t)(l >> 16);
    }
    __syncthreads();
#pragma unroll
    for (int i = 0; i < 8; i++) {
        int o = tid + i * 256;                 // 2048 u32
        int d = o >> 5, kp = o & 31;
        uint32_t vh = *(const uint32_t*)&hiT[d][kp * 2];
        uint32_t vl = *(const uint32_t*)&loT[d][kp * 2];
        size_t oo = ((size_t)(bk * 64 + d) * SEQ + k0) / 2 + kp;  // u32 units
        ((uint32_t*)hi)[oo] = vh;
        ((uint32_t*)lo)[oo] = vl;
    }
}

// ---------------------------------------------------------------------------
// Split-bf16 tensor-core GEMM: 4-stage cp.async pipeline, one sync per chunk
// ---------------------------------------------------------------------------
#define GSTAGES 4
#define GSTAGE_BYTES 32768
#define GEMM_SMEM (GSTAGES * GSTAGE_BYTES)    // 131072

__global__ void __launch_bounds__(256) mma_gemm_kernel(
    const uint16_t* __restrict__ Ahi, const uint16_t* __restrict__ Alo,
    const uint16_t* __restrict__ Bhi, const uint16_t* __restrict__ Blo,
    const float* __restrict__ bias, float* __restrict__ C,
    int M, int N, int K)
{
    extern __shared__ __align__(128) char gsm[];
    const int tid  = threadIdx.x;
    const int lane = tid & 31;
    const int w    = tid >> 5;
    const int mw   = w >> 1;
    const int nw   = w & 1;
    const int rowBase = blockIdx.y * 128;
    const int colBase = blockIdx.x * 128;
    const uint32_t smemBase = smem_u32(gsm);
    const int nChunks = K >> 5;

    float acc[2][8][4];
#pragma unroll
    for (int mt = 0; mt < 2; mt++)
#pragma unroll
        for (int nt = 0; nt < 8; nt++)
#pragma unroll
            for (int j = 0; j < 4; j++) acc[mt][nt][j] = 0.0f;

    auto prefetch = [&](int ch, int stage) {
        if (ch < nChunks) {
            const uint32_t sA = smemBase + stage * GSTAGE_BYTES;
            const uint32_t sB = sA + 16384;
#pragma unroll
            for (int i = 0; i < 8; i++) {
                const int flat = i * 256 + tid;
                const int isB  = flat >> 10;
                const int f    = flat & 1023;
                const int r    = f >> 3, c = f & 7;
                const uint16_t* hp = isB ? Bhi : Ahi;
                const uint16_t* lp = isB ? Blo : Alo;
                const int grow = (isB ? colBase : rowBase) + r;
                const uint16_t* src = ((c < 4) ? hp : lp) + (size_t)grow * K + ch * 32 + (c & 3) * 8;
                const uint32_t dst = (isB ? sB : sA) + r * 128 + ((c ^ (r & 7)) << 4);
                CP_ASYNC16(dst, src);
            }
        }
        CP_COMMIT();
    };

    prefetch(0, 0);
    prefetch(1, 1);
    prefetch(2, 2);

    for (int ch = 0; ch < nChunks; ch++) {
        CP_WAIT2();
        __syncthreads();                       // releases stage (ch+3)&3
        prefetch(ch + 3, (ch + 3) & 3);        // overlaps with compute below
        const uint32_t sA = smemBase + (ch & 3) * GSTAGE_BYTES;
        const uint32_t sB = sA + 16384;

#pragma unroll
        for (int ks = 0; ks < 2; ks++) {
            uint32_t ahi[2][4], alo[2][4];
#pragma unroll
            for (int mt = 0; mt < 2; mt++) {
                const int r  = mw * 32 + mt * 16 + (lane & 7) + ((lane >> 3) & 1) * 8;
                const int cb = ks * 2 + (lane >> 4);
                const uint32_t rowA = sA + r * 128;
                LDMX4(ahi[mt], rowA + ((cb ^ (r & 7)) << 4));
                LDMX4(alo[mt], rowA + (((cb + 4) ^ (r & 7)) << 4));
            }
#pragma unroll
            for (int ntp = 0; ntp < 4; ntp++) {
                const int n  = nw * 64 + ntp * 16 + (lane & 7) + ((lane >> 4) << 3);
                const int cb = ks * 2 + ((lane >> 3) & 1);
                const uint32_t rowB = sB + n * 128;
                uint32_t bh[4], bl[4];
                LDMX4(bh, rowB + ((cb ^ (n & 7)) << 4));
                LDMX4(bl, rowB + (((cb + 4) ^ (n & 7)) << 4));
#pragma unroll
                for (int mt = 0; mt < 2; mt++) {
                    mma16816(acc[mt][2 * ntp],     ahi[mt], bh[0], bh[1]);
                    mma16816(acc[mt][2 * ntp],     ahi[mt], bl[0], bl[1]);
                    mma16816(acc[mt][2 * ntp],     alo[mt], bh[0], bh[1]);
                    mma16816(acc[mt][2 * ntp + 1], ahi[mt], bh[2], bh[3]);
                    mma16816(acc[mt][2 * ntp + 1], ahi[mt], bl[2], bl[3]);
                    mma16816(acc[mt][2 * ntp + 1], alo[mt], bh[2], bh[3]);
                }
            }
        }
    }

    const int g   = lane >> 2;
    const int tg2 = (lane & 3) * 2;
#pragma unroll
    for (int mt = 0; mt < 2; mt++) {
        const int r = rowBase + mw * 32 + mt * 16 + g;
#pragma unroll
        for (int nt = 0; nt < 8; nt++) {
            const int c = colBase + nw * 64 + nt * 8 + tg2;
            float bx = 0.f, by = 0.f;
            if (bias) { bx = bias[c]; by = bias[c + 1]; }
            *(float2*)(C + (size_t)r * N + c)       = make_float2(acc[mt][nt][0] + bx, acc[mt][nt][1] + by);
            *(float2*)(C + (size_t)(r + 8) * N + c) = make_float2(acc[mt][nt][2] + bx, acc[mt][nt][3] + by);
        }
    }
}

// ---------------------------------------------------------------------------
// Tensor-core flash attention: pre-split KV staged via cp.async (2 stages),
// Q rope applied in registers at load.
// Stage layout (u32 words): Khi[4096] Klo[4096] Vhi[4096] Vlo[4096] = 64KB
// ---------------------------------------------------------------------------
#define ATTN_STAGE_WORDS 16384
#define ATTN_SMEM (2 * ATTN_STAGE_WORDS * 4)   // 131072 bytes

__global__ void __launch_bounds__(256) attn_mma_kernel(
    const float* __restrict__ Q,
    const uint16_t* __restrict__ Khi, const uint16_t* __restrict__ Klo,
    const uint16_t* __restrict__ Vhi, const uint16_t* __restrict__ Vlo,
    float* __restrict__ O)
{
    extern __shared__ uint32_t sm[];
    const uint32_t smemBase = smem_u32(sm);

    const int tid  = threadIdx.x;
    const int lane = tid & 31;
    const int w    = tid >> 5;
    const int g    = lane >> 2;
    const int q4   = lane & 3;
    const int tg2  = q4 * 2;

    const int qt = blockIdx.x;
    const int h  = blockIdx.y;
    const int b  = blockIdx.z;
    const int kvh = h & (KVHEADS - 1);
    const int bk  = b * KVHEADS + kvh;

    const int row0 = qt * 128 + w * 16 + g;
    const int row1 = row0 + 8;

    // ---- Q: load raw, rope in registers (partner d+32 = fragment ks+2), scale, split
    uint32_t qhi[4][4], qlo[4][4];
    {
        float2 f0[4], f1[4], f2[4], f3[4];
        const float* Qb  = Q + (size_t)(b * SEQ) * D_MODEL + h * HD;
        const float* Qr0 = Qb + (size_t)row0 * D_MODEL;
        const float* Qr1 = Qb + (size_t)row1 * D_MODEL;
#pragma unroll
        for (int ks = 0; ks < 4; ks++) {
            const int d0 = ks * 16 + tg2;
            f0[ks] = *(const float2*)(Qr0 + d0);
            f1[ks] = *(const float2*)(Qr1 + d0);
            f2[ks] = *(const float2*)(Qr0 + d0 + 8);
            f3[ks] = *(const float2*)(Qr1 + d0 + 8);
        }
        const float* c0p = g_cosT + (row0 << 5);
        const float* s0p = g_sinT + (row0 << 5);
        const float* c1p = g_cosT + (row1 << 5);
        const float* s1p = g_sinT + (row1 << 5);
        auto rot = [](float2& lo, float2& hi, float cx, float sx, float cy, float sy) {
            float nlx = lo.x * cx - hi.x * sx;
            float nhx = hi.x * cx + lo.x * sx;
            float nly = lo.y * cy - hi.y * sy;
            float nhy = hi.y * cy + lo.y * sy;
            lo.x = nlx; hi.x = nhx; lo.y = nly; hi.y = nhy;
        };
#pragma unroll
        for (int ks = 0; ks < 2; ks++) {
            const int hb = ks * 16 + tg2;
            rot(f0[ks], f0[ks + 2], c0p[hb],     s0p[hb],     c0p[hb + 1], s0p[hb + 1]);
            rot(f2[ks], f2[ks + 2], c0p[hb + 8], s0p[hb + 8], c0p[hb + 9], s0p[hb + 9]);
            rot(f1[ks], f1[ks + 2], c1p[hb],     s1p[hb],     c1p[hb + 1], s1p[hb + 1]);
            rot(f3[ks], f3[ks + 2], c1p[hb + 8], s1p[hb + 8], c1p[hb + 9], s1p[hb + 9]);
        }
        const float sc = 0.125f;
#pragma unroll
        for (int ks = 0; ks < 4; ks++) {
            split2(f0[ks].x * sc, f0[ks].y * sc, qhi[ks][0], qlo[ks][0]);
            split2(f1[ks].x * sc, f1[ks].y * sc, qhi[ks][1], qlo[ks][1]);
            split2(f2[ks].x * sc, f2[ks].y * sc, qhi[ks][2], qlo[ks][2]);
            split2(f3[ks].x * sc, f3[ks].y * sc, qhi[ks][3], qlo[ks][3]);
        }
    }

    float o[8][4];
#pragma unroll
    for (int nt = 0; nt < 8; nt++)
#pragma unroll
        for (int j = 0; j < 4; j++) o[nt][j] = 0.0f;
    float m0 = -1e30f, m1 = -1e30f, l0 = 0.0f, l1 = 0.0f;

    const uint16_t* Kh = Khi + (size_t)bk * SEQ * HD;
    const uint16_t* Kl = Klo + (size_t)bk * SEQ * HD;
    const uint16_t* Vh = Vhi + (size_t)bk * HD * SEQ;
    const uint16_t* Vl = Vlo + (size_t)bk * HD * SEQ;

    auto prefetch_tile = [&](int kt, int stage) {
        if (kt < SEQ / 128) {
            const uint32_t KHI = smemBase + stage * (ATTN_STAGE_WORDS * 4);
            const uint32_t KLO = KHI + 16384;
            const uint32_t VHI = KHI + 32768;
            const uint32_t VLO = KHI + 49152;
#pragma unroll
            for (int i = 0; i < 4; i++) {
                const int c = tid + i * 256;           // 1024 chunks
                const int key = c >> 3, j = c & 7;
                const uint16_t* srcH = Kh + (size_t)(kt * 128 + key) * HD + j * 8;
                const uint16_t* srcL = Kl + (size_t)(kt * 128 + key) * HD + j * 8;
                const uint32_t doff = key * 128 + ((j ^ (key & 7)) << 4);
                CP_ASYNC16(KHI + doff, srcH);
                CP_ASYNC16(KLO + doff, srcL);
            }
#pragma unroll
            for (int i = 0; i < 4; i++) {
                const int c = tid + i * 256;           // 1024 chunks
                const int d = c >> 4, cc = c & 15;
                const uint16_t* srcH = Vh + (size_t)d * SEQ + kt * 128 + cc * 8;
                const uint16_t* srcL = Vl + (size_t)d * SEQ + kt * 128 + cc * 8;
                const uint32_t doff = d * 256 + ((cc ^ (d & 7)) << 4);
                CP_ASYNC16(VHI + doff, srcH);
                CP_ASYNC16(VLO + doff, srcL);
            }
        }
        CP_COMMIT();
    };

    prefetch_tile(0, 0);

    for (int kt = 0; kt < SEQ / 128; kt++) {
        if (kt) __syncthreads();               // release stage (kt+1)&1
        prefetch_tile(kt + 1, (kt + 1) & 1);
        CP_WAIT1();
        __syncthreads();

        const uint32_t* stg = sm + (kt & 1) * ATTN_STAGE_WORDS;
        const uint32_t* Ks_hi = stg;
        const uint32_t* Ks_lo = stg + 4096;
        const uint32_t* Vs_hi = stg + 8192;
        const uint32_t* Vs_lo = stg + 12288;

        // ---- S = Q K^T
        float sacc[16][4];
#pragma unroll
        for (int nt = 0; nt < 16; nt++)
#pragma unroll
            for (int j = 0; j < 4; j++) sacc[nt][j] = 0.0f;

#pragma unroll
        for (int ks = 0; ks < 4; ks++) {
#pragma unroll
            for (int nt = 0; nt < 16; nt++) {
                const int key = nt * 8 + g;
                const int base = key * 32;
                const int x = (key & 7) << 2;
                uint32_t bh0 = Ks_hi[base + ((ks * 8 + q4) ^ x)];
                uint32_t bh1 = Ks_hi[base + ((ks * 8 + 4 + q4) ^ x)];
                uint32_t bl0 = Ks_lo[base + ((ks * 8 + q4) ^ x)];
                uint32_t bl1 = Ks_lo[base + ((ks * 8 + 4 + q4) ^ x)];
                mma16816(sacc[nt], qhi[ks], bh0, bh1);
                mma16816(sacc[nt], qhi[ks], bl0, bl1);
                mma16816(sacc[nt], qlo[ks], bh0, bh1);
            }
        }

        // ---- online softmax
        float tmax0 = -1e30f, tmax1 = -1e30f;
#pragma unroll
        for (int nt = 0; nt < 16; nt++) {
            tmax0 = fmaxf(tmax0, fmaxf(sacc[nt][0], sacc[nt][1]));
            tmax1 = fmaxf(tmax1, fmaxf(sacc[nt][2], sacc[nt][3]));
        }
        tmax0 = fmaxf(tmax0, __shfl_xor_sync(0xFFFFFFFF, tmax0, 1));
        tmax0 = fmaxf(tmax0, __shfl_xor_sync(0xFFFFFFFF, tmax0, 2));
        tmax1 = fmaxf(tmax1, __shfl_xor_sync(0xFFFFFFFF, tmax1, 1));
        tmax1 = fmaxf(tmax1, __shfl_xor_sync(0xFFFFFFFF, tmax1, 2));

        const float mn0 = fmaxf(m0, tmax0);
        const float mn1 = fmaxf(m1, tmax1);
        const float sc0 = __expf(m0 - mn0);
        const float sc1 = __expf(m1 - mn1);
        m0 = mn0; m1 = mn1;
        l0 *= sc0; l1 *= sc1;
#pragma unroll
        for (int nt = 0; nt < 8; nt++) {
            o[nt][0] *= sc0; o[nt][1] *= sc0;
            o[nt][2] *= sc1; o[nt][3] *= sc1;
        }

        uint32_t pHi[8][4], pLo[8][4];
        float rs0 = 0.0f, rs1 = 0.0f;
#pragma unroll
        for (int t = 0; t < 8; t++) {
            float p00 = __expf(sacc[2 * t][0] - m0);
            float p01 = __expf(sacc[2 * t][1] - m0);
            float p02 = __expf(sacc[2 * t][2] - m1);
            float p03 = __expf(sacc[2 * t][3] - m1);
            float p10 = __expf(sacc[2 * t + 1][0] - m0);
            float p11 = __expf(sacc[2 * t + 1][1] - m0);
            float p12 = __expf(sacc[2 * t + 1][2] - m1);
            float p13 = __expf(sacc[2 * t + 1][3] - m1);
            rs0 += (p00 + p01) + (p10 + p11);
            rs1 += (p02 + p03) + (p12 + p13);
            split2(p00, p01, pHi[t][0], pLo[t][0]);
            split2(p02, p03, pHi[t][1], pLo[t][1]);
            split2(p10, p11, pHi[t][2], pLo[t][2]);
            split2(p12, p13, pHi[t][3], pLo[t][3]);
        }
        rs0 += __shfl_xor_sync(0xFFFFFFFF, rs0, 1);
        rs0 += __shfl_xor_sync(0xFFFFFFFF, rs0, 2);
        rs1 += __shfl_xor_sync(0xFFFFFFFF, rs1, 1);
        rs1 += __shfl_xor_sync(0xFFFFFFFF, rs1, 2);
        l0 += rs0; l1 += rs1;

        // ---- O += P V
#pragma unroll
        for (int t = 0; t < 8; t++) {
#pragma unroll
            for (int nt = 0; nt < 8; nt++) {
                const int d = nt * 8 + g;
                const int base = d * 64;
                const int x = (d & 7) << 2;
                uint32_t bh0 = Vs_hi[base + ((t * 8 + q4) ^ x)];
                uint32_t bh1 = Vs_hi[base + ((t * 8 + 4 + q4) ^ x)];
                uint32_t bl0 = Vs_lo[base + ((t * 8 + q4) ^ x)];
                uint32_t bl1 = Vs_lo[base + ((t * 8 + 4 + q4) ^ x)];
                mma16816(o[nt], pHi[t], bh0, bh1);
                mma16816(o[nt], pHi[t], bl0, bl1);
                mma16816(o[nt], pLo[t], bh0, bh1);
            }
        }
    }

    const float inv0 = 1.0f / l0;
    const float inv1 = 1.0f / l1;
    float* Ob = O + (size_t)(b * SEQ) * D_MODEL + h * HD;
    float* Or0 = Ob + (size_t)row0 * D_MODEL;
    float* Or1 = Ob + (size_t)row1 * D_MODEL;
#pragma unroll
    for (int nt = 0; nt < 8; nt++) {
        const int c = nt * 8 + tg2;
        *(float2*)(Or0 + c) = make_float2(o[nt][0] * inv0, o[nt][1] * inv0);
        *(float2*)(Or1 + c) = make_float2(o[nt][2] * inv1, o[nt][3] * inv1);
    }
}

// ---------------------------------------------------------------------------
// kernel_launch
// ---------------------------------------------------------------------------
extern "C" void kernel_launch(void* const* d_in, const int* in_sizes, int n_in,
                              void* d_out, int out_size)
{
    const float* q  = (const float*)d_in[0];
    const float* k  = (const float*)d_in[1];
    const float* v  = (const float*)d_in[2];
    const float* Wq = (const float*)d_in[4];
    const float* Wk = (const float*)d_in[5];
    const float* Wv = (const float*)d_in[6];
    const float* Wo = (const float*)d_in[7];
    const float* bo = (const float*)d_in[8];
    float* out = (float*)d_out;

    float *gQ, *gK, *gV, *gAO;
    uint16_t *gAhi, *gAlo, *gBhi, *gBlo, *gKhi, *gKlo, *gVhi, *gVlo;
    cudaGetSymbolAddress((void**)&gQ,   g_Q);
    cudaGetSymbolAddress((void**)&gK,   g_K);
    cudaGetSymbolAddress((void**)&gV,   g_V);
    cudaGetSymbolAddress((void**)&gAO,  g_AO);
    cudaGetSymbolAddress((void**)&gAhi, g_Ahi);
    cudaGetSymbolAddress((void**)&gAlo, g_Alo);
    cudaGetSymbolAddress((void**)&gBhi, g_Bhi);
    cudaGetSymbolAddress((void**)&gBlo, g_Blo);
    cudaGetSymbolAddress((void**)&gKhi, g_Khi);
    cudaGetSymbolAddress((void**)&gKlo, g_Klo);
    cudaGetSymbolAddress((void**)&gVhi, g_Vhi);
    cudaGetSymbolAddress((void**)&gVlo, g_Vlo);

    cudaFuncSetAttribute(mma_gemm_kernel, cudaFuncAttributeMaxDynamicSharedMemorySize, GEMM_SMEM);
    cudaFuncSetAttribute(attn_mma_kernel, cudaFuncAttributeMaxDynamicSharedMemorySize, ATTN_SMEM);

    const int totA2 = NROWS * D_MODEL / 2;

    // RoPE phase table first (convK and attention depend on it)
    rope_table_kernel<<<SEQ * 32 / 256, 256>>>();

    // Q projection
    convB_kernel<<<dim3(D_MODEL / 32, D_MODEL / 32), 256>>>(Wq, gBhi, gBlo, D_MODEL, D_MODEL);
    convA_kernel<<<totA2 / 256, 256>>>(q, gAhi, gAlo, totA2);
    mma_gemm_kernel<<<dim3(D_MODEL / 128, NROWS / 128), 256, GEMM_SMEM>>>(
        gAhi, gAlo, gBhi, gBlo, nullptr, gQ, NROWS, D_MODEL, D_MODEL);

    // K projection -> rope + split
    convB_kernel<<<dim3(KVD / 32, D_MODEL / 32), 256>>>(Wk, gBhi, gBlo, KVD, D_MODEL);
    convA_kernel<<<totA2 / 256, 256>>>(k, gAhi, gAlo, totA2);
    mma_gemm_kernel<<<dim3(KVD / 128, NROWS / 128), 256, GEMM_SMEM>>>(
        gAhi, gAlo, gBhi, gBlo, nullptr, gK, NROWS, KVD, D_MODEL);
    convK_kernel<<<NROWS, 256>>>(gK, gKhi, gKlo);

    // V projection -> transpose + split
    convB_kernel<<<dim3(KVD / 32, D_MODEL / 32), 256>>>(Wv, gBhi, gBlo, KVD, D_MODEL);
    convA_kernel<<<totA2 / 256, 256>>>(v, gAhi, gAlo, totA2);
    mma_gemm_kernel<<<dim3(KVD / 128, NROWS / 128), 256, GEMM_SMEM>>>(
        gAhi, gAlo, gBhi, gBlo, nullptr, gV, NROWS, KVD, D_MODEL);
    convV_kernel<<<dim3(SEQ / 64, BATCH * KVHEADS), 256>>>(gV, gVhi, gVlo);

    // Attention (rope-on-Q fused in)
    attn_mma_kernel<<<dim3(SEQ / 128, QHEADS, BATCH), 256, ATTN_SMEM>>>(
        gQ, gKhi, gKlo, gVhi, gVlo, gAO);

    // Output projection + bias
    convB_kernel<<<dim3(D_MODEL / 32, D_MODEL / 32), 256>>>(Wo, gBhi, gBlo, D_MODEL, D_MODEL);
    convA_kernel<<<totA2 / 256, 256>>>(gAO, gAhi, gAlo, totA2);
    mma_gemm_kernel<<<dim3(D_MODEL / 128, NROWS / 128), 256, GEMM_SMEM>>>(
        gAhi, gAlo, gBhi, gBlo, bo, out, NROWS, D_MODEL, D_MODEL);
}